// round 2
// baseline (speedup 1.0000x reference)
#include <cuda_runtime.h>
#include <cstdint>

#define NN 100000
#define NE 1600000
#define DIM 128
#define SCAN_CHUNK 1024
#define NSB 98            // ceil(NN / SCAN_CHUNK)

#define TILE_N 128
#define KC 64
#define SA_ST 68          // KC + 4 pad (multiple of 4 -> float4-aligned rows)
#define SW_ELEMS (256 * 128)
#define SMEM_LIN ((SW_ELEMS + TILE_N * SA_ST) * 4)   // 165888 B

// ---------------- scratch (no allocations allowed) ----------------
__device__ float g_agg[(size_t)NN * DIM];
__device__ float g_h[(size_t)NN * DIM];
__device__ int   g_rowptr[NN + 1];
__device__ int   g_cursor[NN];
__device__ int   g_col[NE];
__device__ int   g_partials[NSB];
__device__ int   g_is64;

// ---------------- helpers ----------------
__device__ __forceinline__ unsigned long long pack2(float lo, float hi) {
    unsigned long long r;
    asm("mov.b64 %0, {%1, %2};"
        : "=l"(r) : "r"(__float_as_uint(lo)), "r"(__float_as_uint(hi)));
    return r;
}
__device__ __forceinline__ void fma2(unsigned long long& c, unsigned long long a,
                                     unsigned long long b) {
    asm("fma.rn.f32x2 %0, %1, %2, %3;" : "=l"(c) : "l"(a), "l"(b), "l"(c));
}

// edge accessor (dtype-robust)
__device__ __forceinline__ int edge_at(const void* eiv, int idx) {
    if (g_is64) return (int)((const long long*)eiv)[idx];
    return ((const int*)eiv)[idx];
}

// ---------------- dtype detection ----------------
// If the buffer is int64, every high 32-bit word is 0 (indices in [0,1e5)).
// If int32, odd int32 positions hold random indices -> essentially never all 0.
__global__ void k_detect(const int* __restrict__ ei32) {
    int t = threadIdx.x;
    int nz = 0;
    for (int i = t; i < 4096; i += 256) {
        if (ei32[2 * i + 1] != 0) nz = 1;
    }
    nz = __syncthreads_or(nz);
    if (t == 0) g_is64 = nz ? 0 : 1;
}

// ---------------- CSR build ----------------
__global__ void k_zero() {
    int i = blockIdx.x * blockDim.x + threadIdx.x;
    if (i < NN) g_cursor[i] = 0;
}

__global__ void k_hist(const void* __restrict__ eiv) {
    int e = blockIdx.x * blockDim.x + threadIdx.x;
    if (e < NE) {
        int d = edge_at(eiv, NE + e);
        atomicAdd(&g_cursor[d], 1);
    }
}

__global__ void k_scan1() {
    __shared__ int sh[256];
    int t = threadIdx.x;
    int base = blockIdx.x * SCAN_CHUNK + t * 4;
    int v[4];
#pragma unroll
    for (int j = 0; j < 4; j++) v[j] = (base + j < NN) ? g_cursor[base + j] : 0;
    int tsum = v[0] + v[1] + v[2] + v[3];
    sh[t] = tsum;
    __syncthreads();
    for (int d = 1; d < 256; d <<= 1) {
        int o = (t >= d) ? sh[t - d] : 0;
        __syncthreads();
        sh[t] += o;
        __syncthreads();
    }
    int incl = sh[t];
    int p = incl - tsum;  // exclusive
#pragma unroll
    for (int j = 0; j < 4; j++) {
        if (base + j < NN) g_rowptr[base + j] = p;
        p += v[j];
    }
    if (t == 255) g_partials[blockIdx.x] = incl;
}

__global__ void k_scan2() {
    __shared__ int sh[128];
    int t = threadIdx.x;
    int v = (t < NSB) ? g_partials[t] : 0;
    sh[t] = v;
    __syncthreads();
    for (int d = 1; d < 128; d <<= 1) {
        int o = (t >= d) ? sh[t - d] : 0;
        __syncthreads();
        sh[t] += o;
        __syncthreads();
    }
    if (t < NSB) g_partials[t] = sh[t] - v;  // exclusive
}

__global__ void k_scan3() {
    int i = blockIdx.x * blockDim.x + threadIdx.x;
    if (i < NN) {
        int r = g_rowptr[i] + g_partials[i >> 10];
        g_rowptr[i] = r;
        g_cursor[i] = r;
    }
    if (i == 0) g_rowptr[NN] = NE;
}

__global__ void k_fill(const void* __restrict__ eiv) {
    int e = blockIdx.x * blockDim.x + threadIdx.x;
    if (e < NE) {
        int s = edge_at(eiv, e);
        int d = edge_at(eiv, NE + e);
        int pos = atomicAdd(&g_cursor[d], 1);
        g_col[pos] = s;
    }
}

// ---------------- mean aggregation: warp per node, gather ----------------
__global__ void __launch_bounds__(256) k_agg(const float* __restrict__ feat,
                                             float* __restrict__ ag) {
    int gw = (blockIdx.x * blockDim.x + threadIdx.x) >> 5;
    int lane = threadIdx.x & 31;
    if (gw >= NN) return;
    int beg = g_rowptr[gw];
    int end = g_rowptr[gw + 1];
    float4 acc = make_float4(0.f, 0.f, 0.f, 0.f);
    int e = beg;
    for (; e + 4 <= end; e += 4) {
        int s0 = g_col[e], s1 = g_col[e + 1], s2 = g_col[e + 2], s3 = g_col[e + 3];
        float4 v0 = *(const float4*)(feat + (size_t)s0 * DIM + lane * 4);
        float4 v1 = *(const float4*)(feat + (size_t)s1 * DIM + lane * 4);
        float4 v2 = *(const float4*)(feat + (size_t)s2 * DIM + lane * 4);
        float4 v3 = *(const float4*)(feat + (size_t)s3 * DIM + lane * 4);
        acc.x += v0.x + v1.x + v2.x + v3.x;
        acc.y += v0.y + v1.y + v2.y + v3.y;
        acc.z += v0.z + v1.z + v2.z + v3.z;
        acc.w += v0.w + v1.w + v2.w + v3.w;
    }
    for (; e < end; e++) {
        int s = g_col[e];
        float4 v = *(const float4*)(feat + (size_t)s * DIM + lane * 4);
        acc.x += v.x; acc.y += v.y; acc.z += v.z; acc.w += v.w;
    }
    float inv = 1.0f / fmaxf((float)(end - beg), 1.0f);
    acc.x *= inv; acc.y *= inv; acc.z *= inv; acc.w *= inv;
    *(float4*)(ag + (size_t)gw * DIM + lane * 4) = acc;
}

// ---------------- fused linear: out = A@Wl + X@Wr + b (opt relu) ----------------
// Tile: 128 nodes x 128 cols, K = 256 (A cols -> Wl, X cols -> Wr).
// Thread = 8 nodes x 8 cols, acc as f32x2 pairs, FFMA2.
__global__ void __launch_bounds__(256, 1) k_lin(
    const float* __restrict__ A, const float* __restrict__ X,
    const float* __restrict__ Wl, const float* __restrict__ Wr,
    const float* __restrict__ bias, float* __restrict__ out, int do_relu) {
    extern __shared__ float sm[];
    float* sW = sm;               // [256][128]
    float* sA = sm + SW_ELEMS;    // [TILE_N][SA_ST]

    int t = threadIdx.x;
    int cg = t & 15;   // col group: cols cg*8 .. cg*8+7
    int ng = t >> 4;   // node group: nodes ng*8 .. ng*8+7
    int n0 = blockIdx.x * TILE_N;

    // stage W = [Wl ; Wr] into smem
    for (int i = t * 4; i < SW_ELEMS; i += 1024) {
        float4 v;
        if (i < DIM * DIM) v = *(const float4*)(Wl + i);
        else               v = *(const float4*)(Wr + (i - DIM * DIM));
        *(float4*)(sW + i) = v;
    }

    // init accumulators with bias
    unsigned long long acc[8][4];
    {
        const float* bp = bias + cg * 8;
#pragma unroll
        for (int p = 0; p < 4; p++) {
            unsigned long long bb = pack2(bp[2 * p], bp[2 * p + 1]);
#pragma unroll
            for (int i = 0; i < 8; i++) acc[i][p] = bb;
        }
    }

    for (int c = 0; c < 4; c++) {
        const float* src = (c < 2) ? A : X;
        int kbase = (c & 1) * KC;
        __syncthreads();  // previous compute done before overwrite
        for (int i = t * 4; i < TILE_N * KC; i += 1024) {
            int n = i >> 6;
            int kq = i & 63;
            float4 v = make_float4(0.f, 0.f, 0.f, 0.f);
            int gn = n0 + n;
            if (gn < NN) v = *(const float4*)(src + (size_t)gn * DIM + kbase + kq);
            *(float4*)(sA + n * SA_ST + kq) = v;
        }
        __syncthreads();

        const float* sWb = sW + c * KC * DIM + cg * 8;
        const float* sAb = sA + (ng * 8) * SA_ST;
#pragma unroll 2
        for (int kk = 0; kk < KC; kk++) {
            float4 w0 = *(const float4*)(sWb + kk * DIM);
            float4 w1 = *(const float4*)(sWb + kk * DIM + 4);
            unsigned long long w00 = ((const unsigned long long*)&w0)[0];
            unsigned long long w01 = ((const unsigned long long*)&w0)[1];
            unsigned long long w10 = ((const unsigned long long*)&w1)[0];
            unsigned long long w11 = ((const unsigned long long*)&w1)[1];
#pragma unroll
            for (int i = 0; i < 8; i++) {
                float a = sAb[i * SA_ST + kk];
                unsigned long long a2 = pack2(a, a);
                fma2(acc[i][0], w00, a2);
                fma2(acc[i][1], w01, a2);
                fma2(acc[i][2], w10, a2);
                fma2(acc[i][3], w11, a2);
            }
        }
    }

    // write out
#pragma unroll
    for (int i = 0; i < 8; i++) {
        int n = n0 + ng * 8 + i;
        if (n >= NN) continue;
        float r[8];
#pragma unroll
        for (int p = 0; p < 4; p++) {
            float2 f = *(float2*)&acc[i][p];
            r[2 * p] = f.x;
            r[2 * p + 1] = f.y;
        }
        if (do_relu) {
#pragma unroll
            for (int j = 0; j < 8; j++) r[j] = fmaxf(r[j], 0.f);
        }
        float4* op = (float4*)(out + (size_t)n * DIM + cg * 8);
        op[0] = make_float4(r[0], r[1], r[2], r[3]);
        op[1] = make_float4(r[4], r[5], r[6], r[7]);
    }
}

// ---------------- launch ----------------
extern "C" void kernel_launch(void* const* d_in, const int* in_sizes, int n_in,
                              void* d_out, int out_size) {
    const float* x   = (const float*)d_in[0];
    const void*  ei  = d_in[1];
    const float* W1l = (const float*)d_in[2];
    const float* b1  = (const float*)d_in[3];
    const float* W1r = (const float*)d_in[4];
    const float* W2l = (const float*)d_in[5];
    const float* b2  = (const float*)d_in[6];
    const float* W2r = (const float*)d_in[7];
    float*       out = (float*)d_out;

    cudaFuncSetAttribute(k_lin, cudaFuncAttributeMaxDynamicSharedMemorySize, SMEM_LIN);

    float* agg_p = nullptr;
    float* h_p   = nullptr;
    cudaGetSymbolAddress((void**)&agg_p, g_agg);
    cudaGetSymbolAddress((void**)&h_p, g_h);

    int nb_n = (NN + 255) / 256;
    int nb_e = (NE + 255) / 256;
    int nb_w = (NN * 32) / 256;        // warp per node
    int nb_t = (NN + TILE_N - 1) / TILE_N;

    // dtype detection + CSR build (shared by both layers)
    k_detect<<<1, 256>>>((const int*)ei);
    k_zero<<<nb_n, 256>>>();
    k_hist<<<nb_e, 256>>>(ei);
    k_scan1<<<NSB, 256>>>();
    k_scan2<<<1, 128>>>();
    k_scan3<<<nb_n, 256>>>();
    k_fill<<<nb_e, 256>>>(ei);

    // layer 1
    k_agg<<<nb_w, 256>>>(x, agg_p);
    k_lin<<<nb_t, 256, SMEM_LIN>>>(agg_p, x, W1l, W1r, b1, h_p, 1);

    // layer 2
    k_agg<<<nb_w, 256>>>(h_p, agg_p);
    k_lin<<<nb_t, 256, SMEM_LIN>>>(agg_p, h_p, W2l, W2r, b2, out, 0);
}

// round 3
// speedup vs baseline: 1.3830x; 1.3830x over previous
#include <cuda_runtime.h>
#include <cstdint>

#define NN 100000
#define NE 1600000
#define DIM 128

#define TILE_N 256
#define THREADS_LIN 512
#define KC 64
#define SA_ST 68          // KC + 4 pad
#define SW_ELEMS (256 * 128)
#define SA_ELEMS (TILE_N * SA_ST)
#define SMEM_LIN ((SW_ELEMS + SA_ELEMS) * 4)   // 200704 B

// ---------------- scratch (no allocations allowed) ----------------
__device__ float g_agg[(size_t)NN * DIM];
__device__ float g_h[(size_t)NN * DIM];
__device__ int   g_rowptr[NN + 1];
__device__ int   g_cursor[NN];
__device__ int   g_col[NE];
__device__ int   g_is64;

// ---------------- helpers ----------------
__device__ __forceinline__ unsigned long long pack2(float lo, float hi) {
    unsigned long long r;
    asm("mov.b64 %0, {%1, %2};"
        : "=l"(r) : "r"(__float_as_uint(lo)), "r"(__float_as_uint(hi)));
    return r;
}
__device__ __forceinline__ void fma2(unsigned long long& c, unsigned long long a,
                                     unsigned long long b) {
    asm("fma.rn.f32x2 %0, %1, %2, %3;" : "=l"(c) : "l"(a), "l"(b), "l"(c));
}
__device__ __forceinline__ int edge_at(const void* eiv, int idx) {
    if (g_is64) return (int)((const long long*)eiv)[idx];
    return ((const int*)eiv)[idx];
}

// ---------------- init: zero counters + dtype detect ----------------
__global__ void k_init(const int* __restrict__ ei32) {
    int i = blockIdx.x * blockDim.x + threadIdx.x;
    if (i < NN) g_cursor[i] = 0;
    if (blockIdx.x == 0) {
        int nz = 0;
        for (int j = threadIdx.x; j < 4096; j += 256)
            if (ei32[2 * j + 1] != 0) nz = 1;
        nz = __syncthreads_or(nz);
        if (threadIdx.x == 0) g_is64 = nz ? 0 : 1;
    }
}

__global__ void k_hist(const void* __restrict__ eiv) {
    int e = blockIdx.x * blockDim.x + threadIdx.x;
    if (e < NE) {
        int d = edge_at(eiv, NE + e);
        atomicAdd(&g_cursor[d], 1);
    }
}

// ---------------- single-block scan over g_cursor -> g_rowptr ----------------
__global__ void __launch_bounds__(1024) k_scan_all() {
    __shared__ int warp_sums[32];
    int t = threadIdx.x;
    int lane = t & 31;
    int w = t >> 5;
    int carry = 0;
    const int ROUNDS = (NN + 1023) / 1024;   // 98
    for (int r = 0; r < ROUNDS; r++) {
        int i = r * 1024 + t;
        int v = (i < NN) ? g_cursor[i] : 0;
        int s = v;
#pragma unroll
        for (int d = 1; d < 32; d <<= 1) {
            int o = __shfl_up_sync(0xffffffffu, s, d);
            if (lane >= d) s += o;
        }
        if (lane == 31) warp_sums[w] = s;
        __syncthreads();
        if (w == 0) {
            int ws = warp_sums[lane];
#pragma unroll
            for (int d = 1; d < 32; d <<= 1) {
                int o = __shfl_up_sync(0xffffffffu, ws, d);
                if (lane >= d) ws += o;
            }
            warp_sums[lane] = ws;  // inclusive over warps
        }
        __syncthreads();
        int wpre = (w == 0) ? 0 : warp_sums[w - 1];
        int excl = carry + wpre + s - v;
        if (i < NN) {
            g_rowptr[i] = excl;
            g_cursor[i] = excl;
        }
        carry += warp_sums[31];
        __syncthreads();
    }
    if (t == 0) g_rowptr[NN] = NE;
}

__global__ void k_fill(const void* __restrict__ eiv) {
    int e = blockIdx.x * blockDim.x + threadIdx.x;
    if (e < NE) {
        int s = edge_at(eiv, e);
        int d = edge_at(eiv, NE + e);
        int pos = atomicAdd(&g_cursor[d], 1);
        g_col[pos] = s;
    }
}

// ---------------- mean aggregation: warp per node, gather, MLP 8 ----------------
__global__ void __launch_bounds__(256) k_agg(const float* __restrict__ feat,
                                             float* __restrict__ ag) {
    int gw = (blockIdx.x * blockDim.x + threadIdx.x) >> 5;
    int lane = threadIdx.x & 31;
    if (gw >= NN) return;
    int beg = g_rowptr[gw];
    int end = g_rowptr[gw + 1];
    float4 acc = make_float4(0.f, 0.f, 0.f, 0.f);
    int e = beg;
    for (; e + 8 <= end; e += 8) {
        int s[8];
#pragma unroll
        for (int j = 0; j < 8; j++) s[j] = g_col[e + j];
        float4 v[8];
#pragma unroll
        for (int j = 0; j < 8; j++)
            v[j] = *(const float4*)(feat + (size_t)s[j] * DIM + lane * 4);
#pragma unroll
        for (int j = 0; j < 8; j++) {
            acc.x += v[j].x; acc.y += v[j].y; acc.z += v[j].z; acc.w += v[j].w;
        }
    }
    for (; e + 4 <= end; e += 4) {
        int s[4];
#pragma unroll
        for (int j = 0; j < 4; j++) s[j] = g_col[e + j];
#pragma unroll
        for (int j = 0; j < 4; j++) {
            float4 v = *(const float4*)(feat + (size_t)s[j] * DIM + lane * 4);
            acc.x += v.x; acc.y += v.y; acc.z += v.z; acc.w += v.w;
        }
    }
    for (; e < end; e++) {
        int s = g_col[e];
        float4 v = *(const float4*)(feat + (size_t)s * DIM + lane * 4);
        acc.x += v.x; acc.y += v.y; acc.z += v.z; acc.w += v.w;
    }
    float inv = 1.0f / fmaxf((float)(end - beg), 1.0f);
    acc.x *= inv; acc.y *= inv; acc.z *= inv; acc.w *= inv;
    *(float4*)(ag + (size_t)gw * DIM + lane * 4) = acc;
}

// ---------------- fused linear: out = A@Wl + X@Wr + b (opt relu) ----------------
// Tile: 256 nodes x 128 cols, 512 threads (16 warps). Thread = 8 nodes x 8 cols.
__global__ void __launch_bounds__(THREADS_LIN, 1) k_lin(
    const float* __restrict__ A, const float* __restrict__ X,
    const float* __restrict__ Wl, const float* __restrict__ Wr,
    const float* __restrict__ bias, float* __restrict__ out, int do_relu) {
    extern __shared__ float sm[];
    float* sW = sm;               // [256][128]
    float* sA = sm + SW_ELEMS;    // [TILE_N][SA_ST]

    int t = threadIdx.x;
    int cg = t & 15;   // col group: cols cg*8 .. cg*8+7
    int ng = t >> 4;   // node group: nodes ng*8 .. ng*8+7  (0..31)
    int n0 = blockIdx.x * TILE_N;

    // stage W = [Wl ; Wr] into smem
    for (int i = t * 4; i < SW_ELEMS; i += THREADS_LIN * 4) {
        float4 v;
        if (i < DIM * DIM) v = *(const float4*)(Wl + i);
        else               v = *(const float4*)(Wr + (i - DIM * DIM));
        *(float4*)(sW + i) = v;
    }

    // init accumulators with bias
    unsigned long long acc[8][4];
    {
        const float* bp = bias + cg * 8;
#pragma unroll
        for (int p = 0; p < 4; p++) {
            unsigned long long bb = pack2(bp[2 * p], bp[2 * p + 1]);
#pragma unroll
            for (int i = 0; i < 8; i++) acc[i][p] = bb;
        }
    }

    for (int c = 0; c < 4; c++) {
        const float* src = (c < 2) ? A : X;
        int kbase = (c & 1) * KC;
        __syncthreads();  // previous compute done (and W staged) before overwrite
        for (int i = t * 4; i < TILE_N * KC; i += THREADS_LIN * 4) {
            int n = i >> 6;
            int kq = i & 63;
            float4 v = make_float4(0.f, 0.f, 0.f, 0.f);
            int gn = n0 + n;
            if (gn < NN) v = *(const float4*)(src + (size_t)gn * DIM + kbase + kq);
            *(float4*)(sA + n * SA_ST + kq) = v;
        }
        __syncthreads();

        const float* sWb = sW + c * KC * DIM + cg * 8;
        const float* sAb = sA + (ng * 8) * SA_ST;
#pragma unroll 2
        for (int kk = 0; kk < KC; kk++) {
            float4 w0 = *(const float4*)(sWb + kk * DIM);
            float4 w1 = *(const float4*)(sWb + kk * DIM + 4);
            unsigned long long w00 = ((const unsigned long long*)&w0)[0];
            unsigned long long w01 = ((const unsigned long long*)&w0)[1];
            unsigned long long w10 = ((const unsigned long long*)&w1)[0];
            unsigned long long w11 = ((const unsigned long long*)&w1)[1];
#pragma unroll
            for (int i = 0; i < 8; i++) {
                float a = sAb[i * SA_ST + kk];
                unsigned long long a2 = pack2(a, a);
                fma2(acc[i][0], w00, a2);
                fma2(acc[i][1], w01, a2);
                fma2(acc[i][2], w10, a2);
                fma2(acc[i][3], w11, a2);
            }
        }
    }

    // write out
#pragma unroll
    for (int i = 0; i < 8; i++) {
        int n = n0 + ng * 8 + i;
        if (n >= NN) continue;
        float r[8];
#pragma unroll
        for (int p = 0; p < 4; p++) {
            float2 f = *(float2*)&acc[i][p];
            r[2 * p] = f.x;
            r[2 * p + 1] = f.y;
        }
        if (do_relu) {
#pragma unroll
            for (int j = 0; j < 8; j++) r[j] = fmaxf(r[j], 0.f);
        }
        float4* op = (float4*)(out + (size_t)n * DIM + cg * 8);
        op[0] = make_float4(r[0], r[1], r[2], r[3]);
        op[1] = make_float4(r[4], r[5], r[6], r[7]);
    }
}

// ---------------- launch ----------------
extern "C" void kernel_launch(void* const* d_in, const int* in_sizes, int n_in,
                              void* d_out, int out_size) {
    const float* x   = (const float*)d_in[0];
    const void*  ei  = d_in[1];
    const float* W1l = (const float*)d_in[2];
    const float* b1  = (const float*)d_in[3];
    const float* W1r = (const float*)d_in[4];
    const float* W2l = (const float*)d_in[5];
    const float* b2  = (const float*)d_in[6];
    const float* W2r = (const float*)d_in[7];
    float*       out = (float*)d_out;

    cudaFuncSetAttribute(k_lin, cudaFuncAttributeMaxDynamicSharedMemorySize, SMEM_LIN);

    float* agg_p = nullptr;
    float* h_p   = nullptr;
    cudaGetSymbolAddress((void**)&agg_p, g_agg);
    cudaGetSymbolAddress((void**)&h_p, g_h);

    int nb_n = (NN + 255) / 256;
    int nb_e = (NE + 255) / 256;
    int nb_w = (NN * 32) / 256;                  // warp per node
    int nb_t = (NN + TILE_N - 1) / TILE_N;       // 391

    // CSR build (launch indices 0..3)
    k_init<<<nb_n, 256>>>((const int*)ei);
    k_hist<<<nb_e, 256>>>(ei);
    k_scan_all<<<1, 1024>>>();
    k_fill<<<nb_e, 256>>>(ei);

    // layer 1 (agg -> idx 4, lin -> idx 5: ncu -s 5 -c 1 captures k_lin)
    k_agg<<<nb_w, 256>>>(x, agg_p);
    k_lin<<<nb_t, THREADS_LIN, SMEM_LIN>>>(agg_p, x, W1l, W1r, b1, h_p, 1);

    // layer 2
    k_agg<<<nb_w, 256>>>(h_p, agg_p);
    k_lin<<<nb_t, THREADS_LIN, SMEM_LIN>>>(agg_p, h_p, W2l, W2r, b2, out, 0);
}

// round 7
// speedup vs baseline: 1.6433x; 1.1882x over previous
#include <cuda_runtime.h>
#include <cuda_bf16.h>
#include <cstdint>

#define NN 100000
#define NE 1600000
#define DIM 128

// ---- mma GEMM tile config ----
#define TILE_M 128
#define NTILES ((NN + TILE_M - 1) / TILE_M)   // 782
#define SAS_B 144                 // smem row stride in bytes (72 bf16)
#define OFF_AH 0
#define OFF_AL 18432
#define OFF_BH 36864
#define OFF_BL 55296
#define DYN_SMEM 73728

// ---- k_pre block partition ----
#define NB_CONV 12500             // NN*DIM/4 float4 / 256
#define NB_WT   256               // 2*128*256 / 256
#define NB_ZERO 391               // ceil(NN/256)
#define GRID_PRE (NB_CONV + NB_WT + NB_ZERO + 1)

// ---------------- scratch (no allocations allowed) ----------------
__device__ float           g_h[(size_t)NN * DIM];
__device__ __nv_bfloat16   g_xhi[(size_t)NN * DIM];
__device__ __nv_bfloat16   g_xlo[(size_t)NN * DIM];
__device__ __nv_bfloat16   g_ahi[(size_t)NN * DIM];
__device__ __nv_bfloat16   g_alo[(size_t)NN * DIM];
__device__ __nv_bfloat16   g_hhi[(size_t)NN * DIM];
__device__ __nv_bfloat16   g_hlo[(size_t)NN * DIM];
__device__ __nv_bfloat16   g_wth[2][128 * 256];   // W^T hi, [layer][n*256+k]
__device__ __nv_bfloat16   g_wtl[2][128 * 256];   // W^T lo
__device__ int g_rowptr[NN + 1];
__device__ int g_cursor[NN];
__device__ int g_col[NE];
__device__ int g_is64;

// ---------------- helpers ----------------
__device__ __forceinline__ uint32_t smem_u32(const void* p) {
    uint32_t a;
    asm("{ .reg .u64 t; cvta.to.shared.u64 t, %1; cvt.u32.u64 %0, t; }"
        : "=r"(a) : "l"(p));
    return a;
}
__device__ __forceinline__ void ldmx4(uint32_t* r, uint32_t addr) {
    asm volatile("ldmatrix.sync.aligned.m8n8.x4.shared.b16 {%0,%1,%2,%3}, [%4];"
                 : "=r"(r[0]), "=r"(r[1]), "=r"(r[2]), "=r"(r[3]) : "r"(addr));
}
__device__ __forceinline__ void mma16816(float* c, const uint32_t* a, const uint32_t* b) {
    asm volatile(
        "mma.sync.aligned.m16n8k16.row.col.f32.bf16.bf16.f32 "
        "{%0,%1,%2,%3}, {%4,%5,%6,%7}, {%8,%9}, {%0,%1,%2,%3};"
        : "+f"(c[0]), "+f"(c[1]), "+f"(c[2]), "+f"(c[3])
        : "r"(a[0]), "r"(a[1]), "r"(a[2]), "r"(a[3]), "r"(b[0]), "r"(b[1]));
}
__device__ __forceinline__ int edge_at(const void* eiv, int idx) {
    if (g_is64) return (int)((const long long*)eiv)[idx];
    return ((const int*)eiv)[idx];
}
__device__ __forceinline__ void split_store4(__nv_bfloat16* hp, __nv_bfloat16* lp,
                                             float a, float b, float c, float d) {
    __nv_bfloat16 h0 = __float2bfloat16(a), h1 = __float2bfloat16(b);
    __nv_bfloat16 h2 = __float2bfloat16(c), h3 = __float2bfloat16(d);
    __nv_bfloat16 l0 = __float2bfloat16(a - __bfloat162float(h0));
    __nv_bfloat16 l1 = __float2bfloat16(b - __bfloat162float(h1));
    __nv_bfloat16 l2 = __float2bfloat16(c - __bfloat162float(h2));
    __nv_bfloat16 l3 = __float2bfloat16(d - __bfloat162float(h3));
    uint2 hv, lv;
    hv.x = ((uint32_t)__bfloat16_as_ushort(h1) << 16) | __bfloat16_as_ushort(h0);
    hv.y = ((uint32_t)__bfloat16_as_ushort(h3) << 16) | __bfloat16_as_ushort(h2);
    lv.x = ((uint32_t)__bfloat16_as_ushort(l1) << 16) | __bfloat16_as_ushort(l0);
    lv.y = ((uint32_t)__bfloat16_as_ushort(l3) << 16) | __bfloat16_as_ushort(l2);
    *(uint2*)hp = hv;
    *(uint2*)lp = lv;
}
__device__ __forceinline__ uint32_t pack_bf16x2(float a, float b) {
    __nv_bfloat16 h0 = __float2bfloat16(a), h1 = __float2bfloat16(b);
    return ((uint32_t)__bfloat16_as_ushort(h1) << 16) | __bfloat16_as_ushort(h0);
}

// ---------------- pre: x split + W^T split + zero + dtype detect ----------------
__global__ void k_pre(const float* __restrict__ x,
                      const float* __restrict__ W1l, const float* __restrict__ W1r,
                      const float* __restrict__ W2l, const float* __restrict__ W2r,
                      const int* __restrict__ ei32) {
    int b = blockIdx.x, t = threadIdx.x;
    if (b < NB_CONV) {
        int i = b * 256 + t;                       // float4 index
        float4 v = ((const float4*)x)[i];
        split_store4(g_xhi + (size_t)i * 4, g_xlo + (size_t)i * 4, v.x, v.y, v.z, v.w);
    } else if (b < NB_CONV + NB_WT) {
        int g = (b - NB_CONV) * 256 + t;
        int layer = g >> 15;
        int rem = g & 32767;
        int n = rem >> 8;
        int k = rem & 255;
        const float* W = layer ? (k < 128 ? W2l : W2r) : (k < 128 ? W1l : W1r);
        float val = W[(k & 127) * 128 + n];
        __nv_bfloat16 hi = __float2bfloat16(val);
        __nv_bfloat16 lo = __float2bfloat16(val - __bfloat162float(hi));
        g_wth[layer][n * 256 + k] = hi;
        g_wtl[layer][n * 256 + k] = lo;
    } else if (b < NB_CONV + NB_WT + NB_ZERO) {
        int i = (b - NB_CONV - NB_WT) * 256 + t;
        if (i < NN) g_cursor[i] = 0;
    } else {
        int nz = 0;
        for (int j = t; j < 4096; j += 256)
            if (ei32[2 * j + 1] != 0) nz = 1;
        nz = __syncthreads_or(nz);
        if (t == 0) g_is64 = nz ? 0 : 1;
    }
}

__global__ void k_hist(const void* __restrict__ eiv) {
    int e = blockIdx.x * blockDim.x + threadIdx.x;
    if (e < NE) atomicAdd(&g_cursor[edge_at(eiv, NE + e)], 1);
}

// ---------------- single-block scan over g_cursor -> g_rowptr ----------------
__global__ void __launch_bounds__(1024) k_scan_all() {
    __shared__ int warp_sums[32];
    int t = threadIdx.x;
    int lane = t & 31;
    int w = t >> 5;
    int carry = 0;
    const int ROUNDS = (NN + 1023) / 1024;
    for (int r = 0; r < ROUNDS; r++) {
        int i = r * 1024 + t;
        int v = (i < NN) ? g_cursor[i] : 0;
        int s = v;
#pragma unroll
        for (int d = 1; d < 32; d <<= 1) {
            int o = __shfl_up_sync(0xffffffffu, s, d);
            if (lane >= d) s += o;
        }
        if (lane == 31) warp_sums[w] = s;
        __syncthreads();
        if (w == 0) {
            int ws = warp_sums[lane];
#pragma unroll
            for (int d = 1; d < 32; d <<= 1) {
                int o = __shfl_up_sync(0xffffffffu, ws, d);
                if (lane >= d) ws += o;
            }
            warp_sums[lane] = ws;
        }
        __syncthreads();
        int wpre = (w == 0) ? 0 : warp_sums[w - 1];
        int excl = carry + wpre + s - v;
        if (i < NN) {
            g_rowptr[i] = excl;
            g_cursor[i] = excl;
        }
        carry += warp_sums[31];
        __syncthreads();
    }
    if (t == 0) g_rowptr[NN] = NE;
}

__global__ void k_fill(const void* __restrict__ eiv) {
    int e = blockIdx.x * blockDim.x + threadIdx.x;
    if (e < NE) {
        int s = edge_at(eiv, e);
        int d = edge_at(eiv, NE + e);
        g_col[atomicAdd(&g_cursor[d], 1)] = s;
    }
}

// ---------------- mean aggregation: warp/node gather, bf16 hi/lo out ----------------
__global__ void __launch_bounds__(256) k_agg(const float* __restrict__ feat) {
    int gw = (blockIdx.x * blockDim.x + threadIdx.x) >> 5;
    int lane = threadIdx.x & 31;
    if (gw >= NN) return;
    int beg = g_rowptr[gw];
    int end = g_rowptr[gw + 1];
    float4 acc = make_float4(0.f, 0.f, 0.f, 0.f);
    int e = beg;
    for (; e + 8 <= end; e += 8) {
        int s[8];
#pragma unroll
        for (int j = 0; j < 8; j++) s[j] = g_col[e + j];
        float4 v[8];
#pragma unroll
        for (int j = 0; j < 8; j++)
            v[j] = *(const float4*)(feat + (size_t)s[j] * DIM + lane * 4);
#pragma unroll
        for (int j = 0; j < 8; j++) {
            acc.x += v[j].x; acc.y += v[j].y; acc.z += v[j].z; acc.w += v[j].w;
        }
    }
    for (; e < end; e++) {
        int s = g_col[e];
        float4 v = *(const float4*)(feat + (size_t)s * DIM + lane * 4);
        acc.x += v.x; acc.y += v.y; acc.z += v.z; acc.w += v.w;
    }
    float inv = 1.0f / fmaxf((float)(end - beg), 1.0f);
    acc.x *= inv; acc.y *= inv; acc.z *= inv; acc.w *= inv;
    size_t o = (size_t)gw * DIM + lane * 4;
    split_store4(g_ahi + o, g_alo + o, acc.x, acc.y, acc.z, acc.w);
}

// ---------------- mma.sync fused linear ----------------
// D[128x128] = [agg | X](K=256, hi/lo bf16 split, 3 terms) @ W^T + b
// 8 warps: warp_m = wid&3 (32 rows), warp_n = wid>>2 (64 cols).
__global__ void __launch_bounds__(256) k_lin_mma(
    const __nv_bfloat16* __restrict__ Ahi, const __nv_bfloat16* __restrict__ Alo,
    const __nv_bfloat16* __restrict__ Xhi, const __nv_bfloat16* __restrict__ Xlo,
    const __nv_bfloat16* __restrict__ Bh, const __nv_bfloat16* __restrict__ Bl,
    const float* __restrict__ bias, float* __restrict__ outf,
    __nv_bfloat16* __restrict__ ohi, __nv_bfloat16* __restrict__ olo, int do_relu) {
    extern __shared__ char dsm[];
    __shared__ float sbias[128];

    int tid = threadIdx.x;
    int wid = tid >> 5;
    int lane = tid & 31;
    int wm = wid & 3;
    int wn = wid >> 2;
    int n0 = blockIdx.x * TILE_M;

    uint32_t sbase = smem_u32(dsm);
    if (tid < 128) sbias[tid] = bias[tid];

    // per-lane ldmatrix byte offsets (within a buffer)
    int a_off = (wm * 32 + (lane & 15)) * SAS_B + (lane >> 4) * 16;
    int b_off = (wn * 64 + (lane & 7) + ((lane >> 4) << 3)) * SAS_B + ((lane >> 3) & 1) * 16;

    float acc[2][8][4];
#pragma unroll
    for (int mt = 0; mt < 2; mt++)
#pragma unroll
        for (int nt = 0; nt < 8; nt++)
#pragma unroll
            for (int p = 0; p < 4; p++) acc[mt][nt][p] = 0.f;

    for (int kc = 0; kc < 4; kc++) {
        const __nv_bfloat16* ah = (kc < 2) ? Ahi : Xhi;
        const __nv_bfloat16* al = (kc < 2) ? Alo : Xlo;
        int cb = (kc & 1) * 64;
        __syncthreads();
        // stage A hi/lo: 128 rows x 64 bf16
        for (int i = tid; i < 1024; i += 256) {
            int r = i >> 3, c8 = i & 7;
            int so = r * SAS_B + c8 * 16;
            uint4 vh = make_uint4(0, 0, 0, 0), vl = vh;
            int gn = n0 + r;
            if (gn < NN) {
                size_t go = (size_t)gn * DIM + cb + c8 * 8;
                vh = *(const uint4*)(ah + go);
                vl = *(const uint4*)(al + go);
            }
            *(uint4*)(dsm + OFF_AH + so) = vh;
            *(uint4*)(dsm + OFF_AL + so) = vl;
        }
        // stage B hi/lo: 128 n-rows x 64 bf16 (k-chunk)
        for (int i = tid; i < 1024; i += 256) {
            int r = i >> 3, c8 = i & 7;
            int so = r * SAS_B + c8 * 16;
            size_t wo = (size_t)r * 256 + kc * 64 + c8 * 8;
            *(uint4*)(dsm + OFF_BH + so) = *(const uint4*)(Bh + wo);
            *(uint4*)(dsm + OFF_BL + so) = *(const uint4*)(Bl + wo);
        }
        __syncthreads();

#pragma unroll
        for (int term = 0; term < 3; term++) {
            uint32_t Ab = sbase + (term == 2 ? OFF_AL : OFF_AH) + a_off;
            uint32_t Bb = sbase + (term == 1 ? OFF_BL : OFF_BH) + b_off;
#pragma unroll
            for (int ks = 0; ks < 4; ks++) {
                uint32_t afr[2][4];
                ldmx4(afr[0], Ab + ks * 32);
                ldmx4(afr[1], Ab + ks * 32 + 16 * SAS_B);
                uint32_t bfr[8][2];
#pragma unroll
                for (int bp = 0; bp < 4; bp++) {
                    uint32_t q[4];
                    ldmx4(q, Bb + ks * 32 + bp * 16 * SAS_B);
                    bfr[2 * bp][0] = q[0]; bfr[2 * bp][1] = q[1];
                    bfr[2 * bp + 1][0] = q[2]; bfr[2 * bp + 1][1] = q[3];
                }
#pragma unroll
                for (int mt = 0; mt < 2; mt++)
#pragma unroll
                    for (int nt = 0; nt < 8; nt++)
                        mma16816(acc[mt][nt], afr[mt], bfr[nt]);
            }
        }
    }

    // epilogue: bias + relu, direct stores (lane-quad = 32B contiguous)
    int cbase = wn * 64 + (lane & 3) * 2;
#pragma unroll
    for (int mt = 0; mt < 2; mt++) {
        int r0 = n0 + wm * 32 + mt * 16 + (lane >> 2);
#pragma unroll
        for (int nt = 0; nt < 8; nt++) {
            int c = cbase + nt * 8;
            float bx = sbias[c], by = sbias[c + 1];
#pragma unroll
            for (int half = 0; half < 2; half++) {
                int r = r0 + half * 8;
                if (r >= NN) continue;
                float vx = acc[mt][nt][2 * half] + bx;
                float vy = acc[mt][nt][2 * half + 1] + by;
                if (do_relu) { vx = fmaxf(vx, 0.f); vy = fmaxf(vy, 0.f); }
                size_t o = (size_t)r * DIM + c;
                *(float2*)(outf + o) = make_float2(vx, vy);
                if (ohi) {
                    __nv_bfloat16 h0 = __float2bfloat16(vx);
                    __nv_bfloat16 h1 = __float2bfloat16(vy);
                    float l0 = vx - __bfloat162float(h0);
                    float l1 = vy - __bfloat162float(h1);
                    *(uint32_t*)(ohi + o) =
                        ((uint32_t)__bfloat16_as_ushort(h1) << 16) | __bfloat16_as_ushort(h0);
                    *(uint32_t*)(olo + o) = pack_bf16x2(l0, l1);
                }
            }
        }
    }
}

// ---------------- launch ----------------
extern "C" void kernel_launch(void* const* d_in, const int* in_sizes, int n_in,
                              void* d_out, int out_size) {
    const float* x   = (const float*)d_in[0];
    const void*  ei  = d_in[1];
    const float* W1l = (const float*)d_in[2];
    const float* b1  = (const float*)d_in[3];
    const float* W1r = (const float*)d_in[4];
    const float* W2l = (const float*)d_in[5];
    const float* b2  = (const float*)d_in[6];
    const float* W2r = (const float*)d_in[7];
    float*       out = (float*)d_out;

    cudaFuncSetAttribute(k_lin_mma, cudaFuncAttributeMaxDynamicSharedMemorySize, DYN_SMEM);

    float*         h_p = nullptr;
    __nv_bfloat16 *xh, *xl, *ah, *al, *hh, *hl, *w1h, *w1l_, *w2h, *w2l_;
    cudaGetSymbolAddress((void**)&h_p, g_h);
    cudaGetSymbolAddress((void**)&xh, g_xhi);
    cudaGetSymbolAddress((void**)&xl, g_xlo);
    cudaGetSymbolAddress((void**)&ah, g_ahi);
    cudaGetSymbolAddress((void**)&al, g_alo);
    cudaGetSymbolAddress((void**)&hh, g_hhi);
    cudaGetSymbolAddress((void**)&hl, g_hlo);
    {
        __nv_bfloat16 (*wth)[128 * 256];
        __nv_bfloat16 (*wtl)[128 * 256];
        cudaGetSymbolAddress((void**)&wth, g_wth);
        cudaGetSymbolAddress((void**)&wtl, g_wtl);
        w1h = wth[0]; w2h = wth[1];
        w1l_ = wtl[0]; w2l_ = wtl[1];
    }

    int nb_e = (NE + 255) / 256;
    int nb_w = (NN * 32) / 256;                // warp per node

    // 0: pre (x split + W^T split + zero + detect)
    k_pre<<<GRID_PRE, 256>>>(x, W1l, W1r, W2l, W2r, (const int*)ei);
    // 1-3: CSR build (capture lands on k_fill)
    k_hist<<<nb_e, 256>>>(ei);
    k_scan_all<<<1, 1024>>>();
    k_fill<<<nb_e, 256>>>(ei);

    // 4-5: layer 1
    k_agg<<<nb_w, 256>>>(x);
    k_lin_mma<<<NTILES, 256, DYN_SMEM>>>(ah, al, xh, xl, w1h, w1l_, b1, h_p, hh, hl, 1);
    // 6-7: layer 2
    k_agg<<<nb_w, 256>>>(h_p);
    k_lin_mma<<<NTILES, 256, DYN_SMEM>>>(ah, al, hh, hl, w2h, w2l_, b2, out, nullptr, nullptr, 0);
}

// round 9
// speedup vs baseline: 1.7050x; 1.0376x over previous
#include <cuda_runtime.h>
#include <cuda_bf16.h>
#include <cstdint>

#define NN 100000
#define NE 1600000
#define DIM 128

// ---- mma GEMM tile config ----
#define TILE_M 128
#define NTILES ((NN + TILE_M - 1) / TILE_M)   // 782
#define SAS_B 144                 // smem row stride in bytes (72 bf16)
#define OFF_AH 0
#define OFF_AL 18432
#define OFF_BH 36864
#define OFF_BL 55296
#define DYN_SMEM 73728

// ---- k_pre block partition ----
#define NB_CONV 12500             // NN*DIM/4 float4 / 256
#define NB_WT   256               // 2*128*256 / 256
#define NB_ZERO 391               // ceil(NN/256)
#define GRID_PRE (NB_CONV + NB_WT + NB_ZERO + 1)

// ---- fused CSR kernel ----
#define NBLK_CSR 148
#define NTHR_CSR 1024
#define CHUNK 676                 // ceil(NN/148)

// ---------------- scratch (no allocations allowed) ----------------
__device__ float           g_h[(size_t)NN * DIM];
__device__ __nv_bfloat16   g_xhi[(size_t)NN * DIM];
__device__ __nv_bfloat16   g_xlo[(size_t)NN * DIM];
__device__ __nv_bfloat16   g_ahi[(size_t)NN * DIM];
__device__ __nv_bfloat16   g_alo[(size_t)NN * DIM];
__device__ __nv_bfloat16   g_hhi[(size_t)NN * DIM];
__device__ __nv_bfloat16   g_hlo[(size_t)NN * DIM];
__device__ __nv_bfloat16   g_wth[2][128 * 256];   // W^T hi, [layer][n*256+k]
__device__ __nv_bfloat16   g_wtl[2][128 * 256];   // W^T lo
__device__ int g_rowptr[NN + 1];
__device__ int g_cursor[NN];
__device__ int g_col[NE];
__device__ int g_bsum[NBLK_CSR];
__device__ int g_boff[NBLK_CSR];
__device__ int g_arrive[4];
__device__ int g_flagv[4];
__device__ int g_is64;

// ---------------- helpers ----------------
__device__ __forceinline__ uint32_t smem_u32(const void* p) {
    uint32_t a;
    asm("{ .reg .u64 t; cvta.to.shared.u64 t, %1; cvt.u32.u64 %0, t; }"
        : "=r"(a) : "l"(p));
    return a;
}
__device__ __forceinline__ void ldmx4(uint32_t* r, uint32_t addr) {
    asm volatile("ldmatrix.sync.aligned.m8n8.x4.shared.b16 {%0,%1,%2,%3}, [%4];"
                 : "=r"(r[0]), "=r"(r[1]), "=r"(r[2]), "=r"(r[3]) : "r"(addr));
}
__device__ __forceinline__ void mma16816(float* c, const uint32_t* a, const uint32_t* b) {
    asm volatile(
        "mma.sync.aligned.m16n8k16.row.col.f32.bf16.bf16.f32 "
        "{%0,%1,%2,%3}, {%4,%5,%6,%7}, {%8,%9}, {%0,%1,%2,%3};"
        : "+f"(c[0]), "+f"(c[1]), "+f"(c[2]), "+f"(c[3])
        : "r"(a[0]), "r"(a[1]), "r"(a[2]), "r"(a[3]), "r"(b[0]), "r"(b[1]));
}
__device__ __forceinline__ int edge_at(const void* eiv, int idx) {
    if (g_is64) return (int)((const long long*)eiv)[idx];
    return ((const int*)eiv)[idx];
}
__device__ __forceinline__ void split_store4(__nv_bfloat16* hp, __nv_bfloat16* lp,
                                             float a, float b, float c, float d) {
    __nv_bfloat16 h0 = __float2bfloat16(a), h1 = __float2bfloat16(b);
    __nv_bfloat16 h2 = __float2bfloat16(c), h3 = __float2bfloat16(d);
    __nv_bfloat16 l0 = __float2bfloat16(a - __bfloat162float(h0));
    __nv_bfloat16 l1 = __float2bfloat16(b - __bfloat162float(h1));
    __nv_bfloat16 l2 = __float2bfloat16(c - __bfloat162float(h2));
    __nv_bfloat16 l3 = __float2bfloat16(d - __bfloat162float(h3));
    uint2 hv, lv;
    hv.x = ((uint32_t)__bfloat16_as_ushort(h1) << 16) | __bfloat16_as_ushort(h0);
    hv.y = ((uint32_t)__bfloat16_as_ushort(h3) << 16) | __bfloat16_as_ushort(h2);
    lv.x = ((uint32_t)__bfloat16_as_ushort(l1) << 16) | __bfloat16_as_ushort(l0);
    lv.y = ((uint32_t)__bfloat16_as_ushort(l3) << 16) | __bfloat16_as_ushort(l2);
    *(uint2*)hp = hv;
    *(uint2*)lp = lv;
}
__device__ __forceinline__ uint32_t pack_bf16x2(float a, float b) {
    __nv_bfloat16 h0 = __float2bfloat16(a), h1 = __float2bfloat16(b);
    return ((uint32_t)__bfloat16_as_ushort(h1) << 16) | __bfloat16_as_ushort(h0);
}

// grid barrier for k_csr (148 co-resident blocks; counters zeroed by k_pre)
__device__ __forceinline__ void gbar(int i) {
    __syncthreads();
    if (threadIdx.x == 0) {
        __threadfence();
        int a = atomicAdd(&g_arrive[i], 1);
        if (a == NBLK_CSR - 1) {
            atomicExch(&g_flagv[i], 1);
        } else {
            while (!atomicAdd(&g_flagv[i], 0)) {}
        }
        __threadfence();
    }
    __syncthreads();
}

// ---------------- pre: x split + W^T split + zero + dtype detect ----------------
__global__ void k_pre(const float* __restrict__ x,
                      const float* __restrict__ W1l, const float* __restrict__ W1r,
                      const float* __restrict__ W2l, const float* __restrict__ W2r,
                      const int* __restrict__ ei32) {
    int b = blockIdx.x, t = threadIdx.x;
    if (b < NB_CONV) {
        int i = b * 256 + t;                       // float4 index
        float4 v = ((const float4*)x)[i];
        split_store4(g_xhi + (size_t)i * 4, g_xlo + (size_t)i * 4, v.x, v.y, v.z, v.w);
    } else if (b < NB_CONV + NB_WT) {
        int g = (b - NB_CONV) * 256 + t;
        int layer = g >> 15;
        int rem = g & 32767;
        int n = rem >> 8;
        int k = rem & 255;
        const float* W = layer ? (k < 128 ? W2l : W2r) : (k < 128 ? W1l : W1r);
        float val = W[(k & 127) * 128 + n];
        __nv_bfloat16 hi = __float2bfloat16(val);
        __nv_bfloat16 lo = __float2bfloat16(val - __bfloat162float(hi));
        g_wth[layer][n * 256 + k] = hi;
        g_wtl[layer][n * 256 + k] = lo;
    } else if (b < NB_CONV + NB_WT + NB_ZERO) {
        int i = (b - NB_CONV - NB_WT) * 256 + t;
        if (i < NN) g_cursor[i] = 0;
    } else {
        if (t < 4) { g_arrive[t] = 0; g_flagv[t] = 0; }
        int nz = 0;
        for (int j = t; j < 4096; j += 256)
            if (ei32[2 * j + 1] != 0) nz = 1;
        nz = __syncthreads_or(nz);
        if (t == 0) g_is64 = nz ? 0 : 1;
    }
}

// ---------------- fused CSR: hist + scan + fill in one launch ----------------
__global__ void __launch_bounds__(NTHR_CSR, 1) k_csr(const void* __restrict__ eiv) {
    int t = threadIdx.x, b = blockIdx.x;
    int gtid = b * NTHR_CSR + t;
    const int GS = NBLK_CSR * NTHR_CSR;
    __shared__ int wsum[32];
    int lane = t & 31, w = t >> 5;

    // phase 1: histogram
    for (int e = gtid; e < NE; e += GS)
        atomicAdd(&g_cursor[edge_at(eiv, NE + e)], 1);
    gbar(0);

    // phase 2: per-block local scan over CHUNK nodes
    int idx = b * CHUNK + t;
    int v = (t < CHUNK && idx < NN) ? g_cursor[idx] : 0;
    int s = v;
#pragma unroll
    for (int d = 1; d < 32; d <<= 1) {
        int o = __shfl_up_sync(0xffffffffu, s, d);
        if (lane >= d) s += o;
    }
    if (lane == 31) wsum[w] = s;
    __syncthreads();
    if (w == 0) {
        int ws = wsum[lane];
#pragma unroll
        for (int d = 1; d < 32; d <<= 1) {
            int o = __shfl_up_sync(0xffffffffu, ws, d);
            if (lane >= d) ws += o;
        }
        wsum[lane] = ws;
    }
    __syncthreads();
    int excl = (w ? wsum[w - 1] : 0) + s - v;
    if (t == 0) g_bsum[b] = wsum[31];
    __syncthreads();
    gbar(1);

    // phase 3: block 0 scans the 148 block sums
    if (b == 0) {
        int v2 = (t < NBLK_CSR) ? g_bsum[t] : 0;
        int s2 = v2;
#pragma unroll
        for (int d = 1; d < 32; d <<= 1) {
            int o = __shfl_up_sync(0xffffffffu, s2, d);
            if (lane >= d) s2 += o;
        }
        if (lane == 31) wsum[w] = s2;
        __syncthreads();
        if (w == 0) {
            int ws = wsum[lane];
#pragma unroll
            for (int d = 1; d < 32; d <<= 1) {
                int o = __shfl_up_sync(0xffffffffu, ws, d);
                if (lane >= d) ws += o;
            }
            wsum[lane] = ws;
        }
        __syncthreads();
        if (t < NBLK_CSR) g_boff[t] = (w ? wsum[w - 1] : 0) + s2 - v2;
    }
    if (gtid == 0) g_rowptr[NN] = NE;
    gbar(2);

    // phase 4: write rowptr + reset cursor to row start
    int boff = g_boff[b];
    if (t < CHUNK && idx < NN) {
        int r = excl + boff;
        g_rowptr[idx] = r;
        g_cursor[idx] = r;
    }
    gbar(3);

    // phase 5: fill adjacency
    for (int e = gtid; e < NE; e += GS) {
        int src = edge_at(eiv, e);
        int dst = edge_at(eiv, NE + e);
        g_col[atomicAdd(&g_cursor[dst], 1)] = src;
    }
}

// ---------------- mean aggregation: warp/node gather, shfl indices ----------------
__global__ void __launch_bounds__(256) k_agg(const float* __restrict__ feat) {
    int gw = (blockIdx.x * blockDim.x + threadIdx.x) >> 5;
    int lane = threadIdx.x & 31;
    if (gw >= NN) return;
    int beg = g_rowptr[gw];
    int end = g_rowptr[gw + 1];
    float4 acc = make_float4(0.f, 0.f, 0.f, 0.f);
    for (int base = beg; base < end; base += 32) {
        int navail = end - base;
        if (navail > 32) navail = 32;
        int cidx = (base + lane < end) ? g_col[base + lane] : 0;
        int j = 0;
        for (; j + 8 <= navail; j += 8) {
            float4 vv[8];
#pragma unroll
            for (int u = 0; u < 8; u++) {
                int sv = __shfl_sync(0xffffffffu, cidx, j + u);
                vv[u] = *(const float4*)(feat + (size_t)sv * DIM + lane * 4);
            }
#pragma unroll
            for (int u = 0; u < 8; u++) {
                acc.x += vv[u].x; acc.y += vv[u].y;
                acc.z += vv[u].z; acc.w += vv[u].w;
            }
        }
        for (; j < navail; j++) {
            int sv = __shfl_sync(0xffffffffu, cidx, j);
            float4 vv = *(const float4*)(feat + (size_t)sv * DIM + lane * 4);
            acc.x += vv.x; acc.y += vv.y; acc.z += vv.z; acc.w += vv.w;
        }
    }
    float inv = 1.0f / fmaxf((float)(end - beg), 1.0f);
    acc.x *= inv; acc.y *= inv; acc.z *= inv; acc.w *= inv;
    size_t o = (size_t)gw * DIM + lane * 4;
    split_store4(g_ahi + o, g_alo + o, acc.x, acc.y, acc.z, acc.w);
}

// ---------------- mma.sync fused linear ----------------
// D[128x128] = [agg | X](K=256, hi/lo bf16 split, 3 terms) @ W^T + b
// 8 warps: warp_m = wid&3 (32 rows), warp_n = wid>>2 (64 cols).
__global__ void __launch_bounds__(256) k_lin_mma(
    const __nv_bfloat16* __restrict__ Ahi, const __nv_bfloat16* __restrict__ Alo,
    const __nv_bfloat16* __restrict__ Xhi, const __nv_bfloat16* __restrict__ Xlo,
    const __nv_bfloat16* __restrict__ Bh, const __nv_bfloat16* __restrict__ Bl,
    const float* __restrict__ bias, float* __restrict__ outf,
    __nv_bfloat16* __restrict__ ohi, __nv_bfloat16* __restrict__ olo, int do_relu) {
    extern __shared__ char dsm[];
    __shared__ float sbias[128];

    int tid = threadIdx.x;
    int wid = tid >> 5;
    int lane = tid & 31;
    int wm = wid & 3;
    int wn = wid >> 2;
    int n0 = blockIdx.x * TILE_M;

    uint32_t sbase = smem_u32(dsm);
    if (tid < 128) sbias[tid] = bias[tid];

    int a_off = (wm * 32 + (lane & 15)) * SAS_B + (lane >> 4) * 16;
    int b_off = (wn * 64 + (lane & 7) + ((lane >> 4) << 3)) * SAS_B + ((lane >> 3) & 1) * 16;

    float acc[2][8][4];
#pragma unroll
    for (int mt = 0; mt < 2; mt++)
#pragma unroll
        for (int nt = 0; nt < 8; nt++)
#pragma unroll
            for (int p = 0; p < 4; p++) acc[mt][nt][p] = 0.f;

    for (int kc = 0; kc < 4; kc++) {
        const __nv_bfloat16* ah = (kc < 2) ? Ahi : Xhi;
        const __nv_bfloat16* al = (kc < 2) ? Alo : Xlo;
        int cb = (kc & 1) * 64;
        __syncthreads();
        for (int i = tid; i < 1024; i += 256) {
            int r = i >> 3, c8 = i & 7;
            int so = r * SAS_B + c8 * 16;
            uint4 vh = make_uint4(0, 0, 0, 0), vl = vh;
            int gn = n0 + r;
            if (gn < NN) {
                size_t go = (size_t)gn * DIM + cb + c8 * 8;
                vh = *(const uint4*)(ah + go);
                vl = *(const uint4*)(al + go);
            }
            *(uint4*)(dsm + OFF_AH + so) = vh;
            *(uint4*)(dsm + OFF_AL + so) = vl;
        }
        for (int i = tid; i < 1024; i += 256) {
            int r = i >> 3, c8 = i & 7;
            int so = r * SAS_B + c8 * 16;
            size_t wo = (size_t)r * 256 + kc * 64 + c8 * 8;
            *(uint4*)(dsm + OFF_BH + so) = *(const uint4*)(Bh + wo);
            *(uint4*)(dsm + OFF_BL + so) = *(const uint4*)(Bl + wo);
        }
        __syncthreads();

#pragma unroll
        for (int term = 0; term < 3; term++) {
            uint32_t Ab = sbase + (term == 2 ? OFF_AL : OFF_AH) + a_off;
            uint32_t Bb = sbase + (term == 1 ? OFF_BL : OFF_BH) + b_off;
#pragma unroll
            for (int ks = 0; ks < 4; ks++) {
                uint32_t afr[2][4];
                ldmx4(afr[0], Ab + ks * 32);
                ldmx4(afr[1], Ab + ks * 32 + 16 * SAS_B);
                uint32_t bfr[8][2];
#pragma unroll
                for (int bp = 0; bp < 4; bp++) {
                    uint32_t q[4];
                    ldmx4(q, Bb + ks * 32 + bp * 16 * SAS_B);
                    bfr[2 * bp][0] = q[0]; bfr[2 * bp][1] = q[1];
                    bfr[2 * bp + 1][0] = q[2]; bfr[2 * bp + 1][1] = q[3];
                }
#pragma unroll
                for (int mt = 0; mt < 2; mt++)
#pragma unroll
                    for (int nt = 0; nt < 8; nt++)
                        mma16816(acc[mt][nt], afr[mt], bfr[nt]);
            }
        }
    }

    // epilogue: bias + relu, direct stores (lane-quad = 32B contiguous)
    int cbase = wn * 64 + (lane & 3) * 2;
#pragma unroll
    for (int mt = 0; mt < 2; mt++) {
        int r0 = n0 + wm * 32 + mt * 16 + (lane >> 2);
#pragma unroll
        for (int nt = 0; nt < 8; nt++) {
            int c = cbase + nt * 8;
            float bx = sbias[c], by = sbias[c + 1];
#pragma unroll
            for (int half = 0; half < 2; half++) {
                int r = r0 + half * 8;
                if (r >= NN) continue;
                float vx = acc[mt][nt][2 * half] + bx;
                float vy = acc[mt][nt][2 * half + 1] + by;
                if (do_relu) { vx = fmaxf(vx, 0.f); vy = fmaxf(vy, 0.f); }
                size_t o = (size_t)r * DIM + c;
                *(float2*)(outf + o) = make_float2(vx, vy);
                if (ohi) {
                    __nv_bfloat16 h0 = __float2bfloat16(vx);
                    __nv_bfloat16 h1 = __float2bfloat16(vy);
                    float l0 = vx - __bfloat162float(h0);
                    float l1 = vy - __bfloat162float(h1);
                    *(uint32_t*)(ohi + o) =
                        ((uint32_t)__bfloat16_as_ushort(h1) << 16) | __bfloat16_as_ushort(h0);
                    *(uint32_t*)(olo + o) = pack_bf16x2(l0, l1);
                }
            }
        }
    }
}

// ---------------- launch ----------------
extern "C" void kernel_launch(void* const* d_in, const int* in_sizes, int n_in,
                              void* d_out, int out_size) {
    const float* x   = (const float*)d_in[0];
    const void*  ei  = d_in[1];
    const float* W1l = (const float*)d_in[2];
    const float* b1  = (const float*)d_in[3];
    const float* W1r = (const float*)d_in[4];
    const float* W2l = (const float*)d_in[5];
    const float* b2  = (const float*)d_in[6];
    const float* W2r = (const float*)d_in[7];
    float*       out = (float*)d_out;

    cudaFuncSetAttribute(k_lin_mma, cudaFuncAttributeMaxDynamicSharedMemorySize, DYN_SMEM);

    float*         h_p = nullptr;
    __nv_bfloat16 *xh, *xl, *ah, *al, *hh, *hl, *w1h, *w1l_, *w2h, *w2l_;
    cudaGetSymbolAddress((void**)&h_p, g_h);
    cudaGetSymbolAddress((void**)&xh, g_xhi);
    cudaGetSymbolAddress((void**)&xl, g_xlo);
    cudaGetSymbolAddress((void**)&ah, g_ahi);
    cudaGetSymbolAddress((void**)&al, g_alo);
    cudaGetSymbolAddress((void**)&hh, g_hhi);
    cudaGetSymbolAddress((void**)&hl, g_hlo);
    {
        __nv_bfloat16 (*wth)[128 * 256];
        __nv_bfloat16 (*wtl)[128 * 256];
        cudaGetSymbolAddress((void**)&wth, g_wth);
        cudaGetSymbolAddress((void**)&wtl, g_wtl);
        w1h = wth[0]; w2h = wth[1];
        w1l_ = wtl[0]; w2l_ = wtl[1];
    }

    int nb_w = (NN * 32) / 256;                // warp per node

    // 0: pre (x split + W^T split + zero + detect + barrier reset)
    k_pre<<<GRID_PRE, 256>>>(x, W1l, W1r, W2l, W2r, (const int*)ei);
    // 1: fused CSR build (hist + scan + fill)
    k_csr<<<NBLK_CSR, NTHR_CSR>>>(ei);
    // 2: layer-1 aggregation
    k_agg<<<nb_w, 256>>>(x);
    // 3: layer-1 linear  <- ncu capture target
    k_lin_mma<<<NTILES, 256, DYN_SMEM>>>(ah, al, xh, xl, w1h, w1l_, b1, h_p, hh, hl, 1);
    // 4: layer-2 aggregation
    k_agg<<<nb_w, 256>>>(h_p);
    // 5: layer-2 linear
    k_lin_mma<<<NTILES, 256, DYN_SMEM>>>(ah, al, hh, hl, w2h, w2l_, b2, out, nullptr, nullptr, 0);
}

// round 10
// speedup vs baseline: 2.1669x; 1.2709x over previous
#include <cuda_runtime.h>
#include <cuda_bf16.h>
#include <cstdint>

#define NN 100000
#define NE 1600000
#define DIM 128

// ---- mma GEMM tile config ----
#define TILE_M 128
#define NTILES ((NN + TILE_M - 1) / TILE_M)   // 782
#define SAS_B 144                 // smem row stride in bytes (72 bf16)
#define OFF_AH 0
#define OFF_AL 18432
#define OFF_BH 36864
#define OFF_BL 55296
#define STAGE_B 73728             // bytes per pipeline stage
#define DYN_SMEM (2 * STAGE_B)    // 147456

// ---- k_pre block partition ----
#define NB_CONV 12500             // NN*DIM/4 float4 / 256
#define NB_WT   256               // 2*128*256 / 256
#define NB_ZERO 391               // ceil(NN/256)
#define GRID_PRE (NB_CONV + NB_WT + NB_ZERO + 1)

// ---- fused CSR kernel ----
#define NBLK_CSR 148
#define NTHR_CSR 1024
#define CHUNK 676                 // ceil(NN/148)

// ---------------- scratch (no allocations allowed) ----------------
__device__ float           g_h[(size_t)NN * DIM];
__device__ __nv_bfloat16   g_xhi[(size_t)NN * DIM];
__device__ __nv_bfloat16   g_xlo[(size_t)NN * DIM];
__device__ __nv_bfloat16   g_ahi[(size_t)NN * DIM];
__device__ __nv_bfloat16   g_alo[(size_t)NN * DIM];
__device__ __nv_bfloat16   g_hhi[(size_t)NN * DIM];
__device__ __nv_bfloat16   g_hlo[(size_t)NN * DIM];
__device__ __nv_bfloat16   g_wth[2][128 * 256];   // W^T hi, [layer][n*256+k]
__device__ __nv_bfloat16   g_wtl[2][128 * 256];   // W^T lo
__device__ int g_rowptr[NN + 1];
__device__ int g_cursor[NN];
__device__ int g_col[NE];
__device__ int g_bsum[NBLK_CSR];
__device__ int g_boff[NBLK_CSR];
__device__ int g_arrive[4];
__device__ int g_flagv[4];
__device__ int g_is64;

// ---------------- helpers ----------------
__device__ __forceinline__ uint32_t smem_u32(const void* p) {
    uint32_t a;
    asm("{ .reg .u64 t; cvta.to.shared.u64 t, %1; cvt.u32.u64 %0, t; }"
        : "=r"(a) : "l"(p));
    return a;
}
__device__ __forceinline__ void ldmx4(uint32_t* r, uint32_t addr) {
    asm volatile("ldmatrix.sync.aligned.m8n8.x4.shared.b16 {%0,%1,%2,%3}, [%4];"
                 : "=r"(r[0]), "=r"(r[1]), "=r"(r[2]), "=r"(r[3]) : "r"(addr));
}
__device__ __forceinline__ void mma16816(float* c, const uint32_t* a, const uint32_t* b) {
    asm volatile(
        "mma.sync.aligned.m16n8k16.row.col.f32.bf16.bf16.f32 "
        "{%0,%1,%2,%3}, {%4,%5,%6,%7}, {%8,%9}, {%0,%1,%2,%3};"
        : "+f"(c[0]), "+f"(c[1]), "+f"(c[2]), "+f"(c[3])
        : "r"(a[0]), "r"(a[1]), "r"(a[2]), "r"(a[3]), "r"(b[0]), "r"(b[1]));
}
// cp.async 16B; pred==0 -> zero-fill (src-size 0)
__device__ __forceinline__ void cpasync16(uint32_t dst, const void* src, int pred) {
    asm volatile("{\n\t.reg .pred p;\n\tsetp.ne.b32 p, %2, 0;\n\t"
                 "@p  cp.async.cg.shared.global [%0], [%1], 16;\n\t"
                 "@!p cp.async.cg.shared.global [%0], [%1], 16, 0;\n\t}"
                 :: "r"(dst), "l"(src), "r"(pred));
}
__device__ __forceinline__ void cp_commit() {
    asm volatile("cp.async.commit_group;" ::: "memory");
}
template <int N>
__device__ __forceinline__ void cp_wait() {
    asm volatile("cp.async.wait_group %0;" :: "n"(N) : "memory");
}
__device__ __forceinline__ int edge_at(const void* eiv, int idx) {
    if (g_is64) return (int)((const long long*)eiv)[idx];
    return ((const int*)eiv)[idx];
}
__device__ __forceinline__ void split_store4(__nv_bfloat16* hp, __nv_bfloat16* lp,
                                             float a, float b, float c, float d) {
    __nv_bfloat16 h0 = __float2bfloat16(a), h1 = __float2bfloat16(b);
    __nv_bfloat16 h2 = __float2bfloat16(c), h3 = __float2bfloat16(d);
    __nv_bfloat16 l0 = __float2bfloat16(a - __bfloat162float(h0));
    __nv_bfloat16 l1 = __float2bfloat16(b - __bfloat162float(h1));
    __nv_bfloat16 l2 = __float2bfloat16(c - __bfloat162float(h2));
    __nv_bfloat16 l3 = __float2bfloat16(d - __bfloat162float(h3));
    uint2 hv, lv;
    hv.x = ((uint32_t)__bfloat16_as_ushort(h1) << 16) | __bfloat16_as_ushort(h0);
    hv.y = ((uint32_t)__bfloat16_as_ushort(h3) << 16) | __bfloat16_as_ushort(h2);
    lv.x = ((uint32_t)__bfloat16_as_ushort(l1) << 16) | __bfloat16_as_ushort(l0);
    lv.y = ((uint32_t)__bfloat16_as_ushort(l3) << 16) | __bfloat16_as_ushort(l2);
    *(uint2*)hp = hv;
    *(uint2*)lp = lv;
}
__device__ __forceinline__ uint32_t pack_bf16x2(float a, float b) {
    __nv_bfloat16 h0 = __float2bfloat16(a), h1 = __float2bfloat16(b);
    return ((uint32_t)__bfloat16_as_ushort(h1) << 16) | __bfloat16_as_ushort(h0);
}

// grid barrier for k_csr (148 co-resident blocks; counters zeroed by k_pre)
__device__ __forceinline__ void gbar(int i) {
    __syncthreads();
    if (threadIdx.x == 0) {
        __threadfence();
        int a = atomicAdd(&g_arrive[i], 1);
        if (a == NBLK_CSR - 1) {
            atomicExch(&g_flagv[i], 1);
        } else {
            while (!atomicAdd(&g_flagv[i], 0)) {}
        }
        __threadfence();
    }
    __syncthreads();
}

// ---------------- pre: x split + W^T split + zero + dtype detect ----------------
__global__ void k_pre(const float* __restrict__ x,
                      const float* __restrict__ W1l, const float* __restrict__ W1r,
                      const float* __restrict__ W2l, const float* __restrict__ W2r,
                      const int* __restrict__ ei32) {
    int b = blockIdx.x, t = threadIdx.x;
    if (b < NB_CONV) {
        int i = b * 256 + t;                       // float4 index
        float4 v = ((const float4*)x)[i];
        split_store4(g_xhi + (size_t)i * 4, g_xlo + (size_t)i * 4, v.x, v.y, v.z, v.w);
    } else if (b < NB_CONV + NB_WT) {
        int g = (b - NB_CONV) * 256 + t;
        int layer = g >> 15;
        int rem = g & 32767;
        int n = rem >> 8;
        int k = rem & 255;
        const float* W = layer ? (k < 128 ? W2l : W2r) : (k < 128 ? W1l : W1r);
        float val = W[(k & 127) * 128 + n];
        __nv_bfloat16 hi = __float2bfloat16(val);
        __nv_bfloat16 lo = __float2bfloat16(val - __bfloat162float(hi));
        g_wth[layer][n * 256 + k] = hi;
        g_wtl[layer][n * 256 + k] = lo;
    } else if (b < NB_CONV + NB_WT + NB_ZERO) {
        int i = (b - NB_CONV - NB_WT) * 256 + t;
        if (i < NN) g_cursor[i] = 0;
    } else {
        if (t < 4) { g_arrive[t] = 0; g_flagv[t] = 0; }
        int nz = 0;
        for (int j = t; j < 4096; j += 256)
            if (ei32[2 * j + 1] != 0) nz = 1;
        nz = __syncthreads_or(nz);
        if (t == 0) g_is64 = nz ? 0 : 1;
    }
}

// ---------------- fused CSR: hist + scan + fill in one launch ----------------
__global__ void __launch_bounds__(NTHR_CSR, 1) k_csr(const void* __restrict__ eiv) {
    int t = threadIdx.x, b = blockIdx.x;
    int gtid = b * NTHR_CSR + t;
    const int GS = NBLK_CSR * NTHR_CSR;
    __shared__ int wsum[32];
    int lane = t & 31, w = t >> 5;

    for (int e = gtid; e < NE; e += GS)
        atomicAdd(&g_cursor[edge_at(eiv, NE + e)], 1);
    gbar(0);

    int idx = b * CHUNK + t;
    int v = (t < CHUNK && idx < NN) ? g_cursor[idx] : 0;
    int s = v;
#pragma unroll
    for (int d = 1; d < 32; d <<= 1) {
        int o = __shfl_up_sync(0xffffffffu, s, d);
        if (lane >= d) s += o;
    }
    if (lane == 31) wsum[w] = s;
    __syncthreads();
    if (w == 0) {
        int ws = wsum[lane];
#pragma unroll
        for (int d = 1; d < 32; d <<= 1) {
            int o = __shfl_up_sync(0xffffffffu, ws, d);
            if (lane >= d) ws += o;
        }
        wsum[lane] = ws;
    }
    __syncthreads();
    int excl = (w ? wsum[w - 1] : 0) + s - v;
    if (t == 0) g_bsum[b] = wsum[31];
    __syncthreads();
    gbar(1);

    if (b == 0) {
        int v2 = (t < NBLK_CSR) ? g_bsum[t] : 0;
        int s2 = v2;
#pragma unroll
        for (int d = 1; d < 32; d <<= 1) {
            int o = __shfl_up_sync(0xffffffffu, s2, d);
            if (lane >= d) s2 += o;
        }
        if (lane == 31) wsum[w] = s2;
        __syncthreads();
        if (w == 0) {
            int ws = wsum[lane];
#pragma unroll
            for (int d = 1; d < 32; d <<= 1) {
                int o = __shfl_up_sync(0xffffffffu, ws, d);
                if (lane >= d) ws += o;
            }
            wsum[lane] = ws;
        }
        __syncthreads();
        if (t < NBLK_CSR) g_boff[t] = (w ? wsum[w - 1] : 0) + s2 - v2;
    }
    if (gtid == 0) g_rowptr[NN] = NE;
    gbar(2);

    int boff = g_boff[b];
    if (t < CHUNK && idx < NN) {
        int r = excl + boff;
        g_rowptr[idx] = r;
        g_cursor[idx] = r;
    }
    gbar(3);

    for (int e = gtid; e < NE; e += GS) {
        int src = edge_at(eiv, e);
        int dst = edge_at(eiv, NE + e);
        g_col[atomicAdd(&g_cursor[dst], 1)] = src;
    }
}

// ---------------- mean aggregation: warp/node gather, shfl indices ----------------
__global__ void __launch_bounds__(256) k_agg(const float* __restrict__ feat) {
    int gw = (blockIdx.x * blockDim.x + threadIdx.x) >> 5;
    int lane = threadIdx.x & 31;
    if (gw >= NN) return;
    int beg = g_rowptr[gw];
    int end = g_rowptr[gw + 1];
    float4 acc = make_float4(0.f, 0.f, 0.f, 0.f);
    for (int base = beg; base < end; base += 32) {
        int navail = end - base;
        if (navail > 32) navail = 32;
        int cidx = (base + lane < end) ? g_col[base + lane] : 0;
        int j = 0;
        for (; j + 8 <= navail; j += 8) {
            float4 vv[8];
#pragma unroll
            for (int u = 0; u < 8; u++) {
                int sv = __shfl_sync(0xffffffffu, cidx, j + u);
                vv[u] = *(const float4*)(feat + (size_t)sv * DIM + lane * 4);
            }
#pragma unroll
            for (int u = 0; u < 8; u++) {
                acc.x += vv[u].x; acc.y += vv[u].y;
                acc.z += vv[u].z; acc.w += vv[u].w;
            }
        }
        for (; j < navail; j++) {
            int sv = __shfl_sync(0xffffffffu, cidx, j);
            float4 vv = *(const float4*)(feat + (size_t)sv * DIM + lane * 4);
            acc.x += vv.x; acc.y += vv.y; acc.z += vv.z; acc.w += vv.w;
        }
    }
    float inv = 1.0f / fmaxf((float)(end - beg), 1.0f);
    acc.x *= inv; acc.y *= inv; acc.z *= inv; acc.w *= inv;
    size_t o = (size_t)gw * DIM + lane * 4;
    split_store4(g_ahi + o, g_alo + o, acc.x, acc.y, acc.z, acc.w);
}

// ---------------- mma.sync fused linear, cp.async double-buffered ----------------
// D[128x128] = [agg | X](K=256, hi/lo bf16 split, 3 terms) @ W^T + b
// 512 threads, 16 warps: wm = wid&7 (16 rows), wn = wid>>3 (64 cols).
__global__ void __launch_bounds__(512) k_lin_mma(
    const __nv_bfloat16* __restrict__ Ahi, const __nv_bfloat16* __restrict__ Alo,
    const __nv_bfloat16* __restrict__ Xhi, const __nv_bfloat16* __restrict__ Xlo,
    const __nv_bfloat16* __restrict__ Bh, const __nv_bfloat16* __restrict__ Bl,
    const float* __restrict__ bias, float* __restrict__ outf,
    __nv_bfloat16* __restrict__ ohi, __nv_bfloat16* __restrict__ olo, int do_relu) {
    extern __shared__ char dsm[];
    __shared__ float sbias[128];

    int tid = threadIdx.x;
    int wid = tid >> 5;
    int lane = tid & 31;
    int wm = wid & 7;
    int wn = wid >> 3;
    int n0 = blockIdx.x * TILE_M;

    uint32_t sbase = smem_u32(dsm);
    if (tid < 128) sbias[tid] = bias[tid];

    int a_off = (wm * 16 + (lane & 15)) * SAS_B + (lane >> 4) * 16;
    int b_off = (wn * 64 + (lane & 7) + ((lane >> 4) << 3)) * SAS_B + ((lane >> 3) & 1) * 16;

    float acc[8][4];
#pragma unroll
    for (int nt = 0; nt < 8; nt++)
#pragma unroll
        for (int p = 0; p < 4; p++) acc[nt][p] = 0.f;

    // stage issuer: chunk kc -> stage buffer sg
    auto stage_issue = [&](int kc, int sg) {
        const __nv_bfloat16* ah = (kc < 2) ? Ahi : Xhi;
        const __nv_bfloat16* al = (kc < 2) ? Alo : Xlo;
        int cb = (kc & 1) * 64;
        uint32_t sb = sbase + sg * STAGE_B;
#pragma unroll
        for (int it = 0; it < 8; it++) {
            int i = it * 512 + tid;
            int piece = i >> 10;          // 0:AH 1:AL 2:BH 3:BL
            int rem = i & 1023;
            int r = rem >> 3, c8 = rem & 7;
            uint32_t dst = sb + piece * 18432 + r * SAS_B + c8 * 16;
            if (piece < 2) {
                int gn = n0 + r;
                const __nv_bfloat16* src = (piece == 0) ? ah : al;
                // clamp pointer for OOB rows (not dereferenced: src-size 0)
                int gnc = (gn < NN) ? gn : 0;
                cpasync16(dst, src + (size_t)gnc * DIM + cb + c8 * 8, gn < NN);
            } else {
                const __nv_bfloat16* src = (piece == 2) ? Bh : Bl;
                cpasync16(dst, src + (size_t)r * 256 + kc * 64 + c8 * 8, 1);
            }
        }
        cp_commit();
    };

    stage_issue(0, 0);

    for (int kc = 0; kc < 4; kc++) {
        if (kc < 3) stage_issue(kc + 1, (kc + 1) & 1);
        if (kc < 3) cp_wait<1>(); else cp_wait<0>();
        __syncthreads();

        uint32_t sb = sbase + (kc & 1) * STAGE_B;
#pragma unroll
        for (int term = 0; term < 3; term++) {
            uint32_t Ab = sb + (term == 2 ? OFF_AL : OFF_AH) + a_off;
            uint32_t Bb = sb + (term == 1 ? OFF_BL : OFF_BH) + b_off;
#pragma unroll
            for (int ks = 0; ks < 4; ks++) {
                uint32_t afr[4];
                ldmx4(afr, Ab + ks * 32);
                uint32_t bfr[8][2];
#pragma unroll
                for (int bp = 0; bp < 4; bp++) {
                    uint32_t q[4];
                    ldmx4(q, Bb + ks * 32 + bp * 16 * SAS_B);
                    bfr[2 * bp][0] = q[0]; bfr[2 * bp][1] = q[1];
                    bfr[2 * bp + 1][0] = q[2]; bfr[2 * bp + 1][1] = q[3];
                }
#pragma unroll
                for (int nt = 0; nt < 8; nt++)
                    mma16816(acc[nt], afr, bfr[nt]);
            }
        }
        __syncthreads();
    }

    // epilogue: bias + relu, direct stores (lane-quad = 32B contiguous)
    int cbase = wn * 64 + (lane & 3) * 2;
    int r0 = n0 + wm * 16 + (lane >> 2);
#pragma unroll
    for (int nt = 0; nt < 8; nt++) {
        int c = cbase + nt * 8;
        float bx = sbias[c], by = sbias[c + 1];
#pragma unroll
        for (int half = 0; half < 2; half++) {
            int r = r0 + half * 8;
            if (r >= NN) continue;
            float vx = acc[nt][2 * half] + bx;
            float vy = acc[nt][2 * half + 1] + by;
            if (do_relu) { vx = fmaxf(vx, 0.f); vy = fmaxf(vy, 0.f); }
            size_t o = (size_t)r * DIM + c;
            *(float2*)(outf + o) = make_float2(vx, vy);
            if (ohi) {
                __nv_bfloat16 h0 = __float2bfloat16(vx);
                __nv_bfloat16 h1 = __float2bfloat16(vy);
                float l0 = vx - __bfloat162float(h0);
                float l1 = vy - __bfloat162float(h1);
                *(uint32_t*)(ohi + o) =
                    ((uint32_t)__bfloat16_as_ushort(h1) << 16) | __bfloat16_as_ushort(h0);
                *(uint32_t*)(olo + o) = pack_bf16x2(l0, l1);
            }
        }
    }
}

// ---------------- launch ----------------
extern "C" void kernel_launch(void* const* d_in, const int* in_sizes, int n_in,
                              void* d_out, int out_size) {
    const float* x   = (const float*)d_in[0];
    const void*  ei  = d_in[1];
    const float* W1l = (const float*)d_in[2];
    const float* b1  = (const float*)d_in[3];
    const float* W1r = (const float*)d_in[4];
    const float* W2l = (const float*)d_in[5];
    const float* b2  = (const float*)d_in[6];
    const float* W2r = (const float*)d_in[7];
    float*       out = (float*)d_out;

    cudaFuncSetAttribute(k_lin_mma, cudaFuncAttributeMaxDynamicSharedMemorySize, DYN_SMEM);

    float*         h_p = nullptr;
    __nv_bfloat16 *xh, *xl, *ah, *al, *hh, *hl, *w1h, *w1l_, *w2h, *w2l_;
    cudaGetSymbolAddress((void**)&h_p, g_h);
    cudaGetSymbolAddress((void**)&xh, g_xhi);
    cudaGetSymbolAddress((void**)&xl, g_xlo);
    cudaGetSymbolAddress((void**)&ah, g_ahi);
    cudaGetSymbolAddress((void**)&al, g_alo);
    cudaGetSymbolAddress((void**)&hh, g_hhi);
    cudaGetSymbolAddress((void**)&hl, g_hlo);
    {
        __nv_bfloat16 (*wth)[128 * 256];
        __nv_bfloat16 (*wtl)[128 * 256];
        cudaGetSymbolAddress((void**)&wth, g_wth);
        cudaGetSymbolAddress((void**)&wtl, g_wtl);
        w1h = wth[0]; w2h = wth[1];
        w1l_ = wtl[0]; w2l_ = wtl[1];
    }

    int nb_w = (NN * 32) / 256;                // warp per node

    // 0: pre (x split + W^T split + zero + detect + barrier reset)
    k_pre<<<GRID_PRE, 256>>>(x, W1l, W1r, W2l, W2r, (const int*)ei);
    // 1: fused CSR build (hist + scan + fill)
    k_csr<<<NBLK_CSR, NTHR_CSR>>>(ei);
    // 2: layer-1 aggregation
    k_agg<<<nb_w, 256>>>(x);
    // 3: layer-1 linear  <- ncu capture target
    k_lin_mma<<<NTILES, 512, DYN_SMEM>>>(ah, al, xh, xl, w1h, w1l_, b1, h_p, hh, hl, 1);
    // 4: layer-2 aggregation
    k_agg<<<nb_w, 256>>>(h_p);
    // 5: layer-2 linear
    k_lin_mma<<<NTILES, 512, DYN_SMEM>>>(ah, al, hh, hl, w2h, w2l_, b2, out, nullptr, nullptr, 0);
}

// round 13
// speedup vs baseline: 2.9843x; 1.3772x over previous
#include <cuda_runtime.h>
#include <cuda_fp16.h>
#include <cstdint>

#define NN 100000
#define NE 1600000
#define DIM 128

// ---- mma GEMM tile config ----
#define TILE_M 128
#define NTILES ((NN + TILE_M - 1) / TILE_M)   // 782
#define SAS_B 144                 // smem row stride in bytes (72 fp16)
#define OFF_AH 0
#define OFF_AL 18432
#define OFF_BH 36864
#define STAGE_B 55296             // bytes per pipeline stage (AH+AL+BH)
#define DYN_SMEM (2 * STAGE_B)    // 110592

// ---- k_pre block partition ----
#define NB_CONV 12500             // NN*DIM/4 float4 / 256
#define NB_WT   256               // 2*128*256 / 256
#define NB_ZERO 391               // ceil(NN/256)
#define GRID_PRE (NB_CONV + NB_WT + NB_ZERO + 1)

// ---- fused CSR kernel ----
#define NBLK_CSR 148
#define NTHR_CSR 1024
#define CHUNK 676                 // ceil(NN/148)

// ---------------- scratch (no allocations allowed) ----------------
__device__ __half g_xhi[(size_t)NN * DIM];
__device__ __half g_xlo[(size_t)NN * DIM];
__device__ __half g_ahi[(size_t)NN * DIM];
__device__ __half g_alo[(size_t)NN * DIM];
__device__ __half g_hhi[(size_t)NN * DIM];
__device__ __half g_hlo[(size_t)NN * DIM];
__device__ __half g_wth[2][128 * 256];   // W^T fp16, [layer][n*256+k]
__device__ int g_rowptr[NN + 1];
__device__ int g_cursor[NN];
__device__ int g_col[NE];
__device__ int g_bsum[NBLK_CSR];
__device__ int g_boff[NBLK_CSR];
__device__ int g_arrive[4];
__device__ int g_flagv[4];
__device__ int g_is64;

// ---------------- helpers ----------------
__device__ __forceinline__ uint32_t smem_u32(const void* p) {
    uint32_t a;
    asm("{ .reg .u64 t; cvta.to.shared.u64 t, %1; cvt.u32.u64 %0, t; }"
        : "=r"(a) : "l"(p));
    return a;
}
__device__ __forceinline__ void ldmx4(uint32_t* r, uint32_t addr) {
    asm volatile("ldmatrix.sync.aligned.m8n8.x4.shared.b16 {%0,%1,%2,%3}, [%4];"
                 : "=r"(r[0]), "=r"(r[1]), "=r"(r[2]), "=r"(r[3]) : "r"(addr));
}
__device__ __forceinline__ void mma16816(float* c, const uint32_t* a, const uint32_t* b) {
    asm volatile(
        "mma.sync.aligned.m16n8k16.row.col.f32.f16.f16.f32 "
        "{%0,%1,%2,%3}, {%4,%5,%6,%7}, {%8,%9}, {%0,%1,%2,%3};"
        : "+f"(c[0]), "+f"(c[1]), "+f"(c[2]), "+f"(c[3])
        : "r"(a[0]), "r"(a[1]), "r"(a[2]), "r"(a[3]), "r"(b[0]), "r"(b[1]));
}
// cp.async 16B; pred==0 -> zero-fill (src-size 0)
__device__ __forceinline__ void cpasync16(uint32_t dst, const void* src, int pred) {
    asm volatile("{\n\t.reg .pred p;\n\tsetp.ne.b32 p, %2, 0;\n\t"
                 "@p  cp.async.cg.shared.global [%0], [%1], 16;\n\t"
                 "@!p cp.async.cg.shared.global [%0], [%1], 16, 0;\n\t}"
                 :: "r"(dst), "l"(src), "r"(pred));
}
__device__ __forceinline__ void cp_commit() {
    asm volatile("cp.async.commit_group;" ::: "memory");
}
template <int N>
__device__ __forceinline__ void cp_wait() {
    asm volatile("cp.async.wait_group %0;" :: "n"(N) : "memory");
}
__device__ __forceinline__ int edge_at(const void* eiv, int idx) {
    if (g_is64) return (int)((const long long*)eiv)[idx];
    return ((const int*)eiv)[idx];
}
__device__ __forceinline__ uint32_t pack_h2(__half a, __half b) {
    return ((uint32_t)__half_as_ushort(b) << 16) | __half_as_ushort(a);
}
// fp16 hi/lo split of 4 floats -> two uint2 (8 halves)
__device__ __forceinline__ void split_store4(__half* hp, __half* lp,
                                             float a, float b, float c, float d) {
    __half h0 = __float2half_rn(a), h1 = __float2half_rn(b);
    __half h2 = __float2half_rn(c), h3 = __float2half_rn(d);
    __half l0 = __float2half_rn(a - __half2float(h0));
    __half l1 = __float2half_rn(b - __half2float(h1));
    __half l2 = __float2half_rn(c - __half2float(h2));
    __half l3 = __float2half_rn(d - __half2float(h3));
    uint2 hv, lv;
    hv.x = pack_h2(h0, h1); hv.y = pack_h2(h2, h3);
    lv.x = pack_h2(l0, l1); lv.y = pack_h2(l2, l3);
    *(uint2*)hp = hv;
    *(uint2*)lp = lv;
}

// grid barrier for k_csr (148 co-resident blocks; counters zeroed by k_pre)
__device__ __forceinline__ void gbar(int i) {
    __syncthreads();
    if (threadIdx.x == 0) {
        __threadfence();
        int a = atomicAdd(&g_arrive[i], 1);
        if (a == NBLK_CSR - 1) {
            atomicExch(&g_flagv[i], 1);
        } else {
            while (!atomicAdd(&g_flagv[i], 0)) {}
        }
        __threadfence();
    }
    __syncthreads();
}

// ---------------- pre: x split + W^T fp16 + zero + dtype detect ----------------
__global__ void k_pre(const float* __restrict__ x,
                      const float* __restrict__ W1l, const float* __restrict__ W1r,
                      const float* __restrict__ W2l, const float* __restrict__ W2r,
                      const int* __restrict__ ei32) {
    int b = blockIdx.x, t = threadIdx.x;
    if (b < NB_CONV) {
        int i = b * 256 + t;                       // float4 index
        float4 v = ((const float4*)x)[i];
        split_store4(g_xhi + (size_t)i * 4, g_xlo + (size_t)i * 4, v.x, v.y, v.z, v.w);
    } else if (b < NB_CONV + NB_WT) {
        int g = (b - NB_CONV) * 256 + t;
        int layer = g >> 15;
        int rem = g & 32767;
        int n = rem >> 8;
        int k = rem & 255;
        const float* W = layer ? (k < 128 ? W2l : W2r) : (k < 128 ? W1l : W1r);
        g_wth[layer][n * 256 + k] = __float2half_rn(W[(k & 127) * 128 + n]);
    } else if (b < NB_CONV + NB_WT + NB_ZERO) {
        int i = (b - NB_CONV - NB_WT) * 256 + t;
        if (i < NN) g_cursor[i] = 0;
    } else {
        if (t < 4) { g_arrive[t] = 0; g_flagv[t] = 0; }
        int nz = 0;
        for (int j = t; j < 4096; j += 256)
            if (ei32[2 * j + 1] != 0) nz = 1;
        nz = __syncthreads_or(nz);
        if (t == 0) g_is64 = nz ? 0 : 1;
    }
}

// ---------------- fused CSR: hist + scan + fill in one launch ----------------
__global__ void __launch_bounds__(NTHR_CSR, 1) k_csr(const void* __restrict__ eiv) {
    int t = threadIdx.x, b = blockIdx.x;
    int gtid = b * NTHR_CSR + t;
    const int GS = NBLK_CSR * NTHR_CSR;
    __shared__ int wsum[32];
    int lane = t & 31, w = t >> 5;

    for (int e = gtid; e < NE; e += GS)
        atomicAdd(&g_cursor[edge_at(eiv, NE + e)], 1);
    gbar(0);

    int idx = b * CHUNK + t;
    int v = (t < CHUNK && idx < NN) ? g_cursor[idx] : 0;
    int s = v;
#pragma unroll
    for (int d = 1; d < 32; d <<= 1) {
        int o = __shfl_up_sync(0xffffffffu, s, d);
        if (lane >= d) s += o;
    }
    if (lane == 31) wsum[w] = s;
    __syncthreads();
    if (w == 0) {
        int ws = wsum[lane];
#pragma unroll
        for (int d = 1; d < 32; d <<= 1) {
            int o = __shfl_up_sync(0xffffffffu, ws, d);
            if (lane >= d) ws += o;
        }
        wsum[lane] = ws;
    }
    __syncthreads();
    int excl = (w ? wsum[w - 1] : 0) + s - v;
    if (t == 0) g_bsum[b] = wsum[31];
    __syncthreads();
    gbar(1);

    if (b == 0) {
        int v2 = (t < NBLK_CSR) ? g_bsum[t] : 0;
        int s2 = v2;
#pragma unroll
        for (int d = 1; d < 32; d <<= 1) {
            int o = __shfl_up_sync(0xffffffffu, s2, d);
            if (lane >= d) s2 += o;
        }
        if (lane == 31) wsum[w] = s2;
        __syncthreads();
        if (w == 0) {
            int ws = wsum[lane];
#pragma unroll
            for (int d = 1; d < 32; d <<= 1) {
                int o = __shfl_up_sync(0xffffffffu, ws, d);
                if (lane >= d) ws += o;
            }
            wsum[lane] = ws;
        }
        __syncthreads();
        if (t < NBLK_CSR) g_boff[t] = (w ? wsum[w - 1] : 0) + s2 - v2;
    }
    if (gtid == 0) g_rowptr[NN] = NE;
    gbar(2);

    int boff = g_boff[b];
    if (t < CHUNK && idx < NN) {
        int r = excl + boff;
        g_rowptr[idx] = r;
        g_cursor[idx] = r;
    }
    gbar(3);

    for (int e = gtid; e < NE; e += GS) {
        int src = edge_at(eiv, e);
        int dst = edge_at(eiv, NE + e);
        g_col[atomicAdd(&g_cursor[dst], 1)] = src;
    }
}

// ---------------- mean aggregation over fp16 features (256B/row) ----------------
// warp per node; lane covers 4 feature elements (uint2 = 4 halves).
__global__ void __launch_bounds__(256) k_agg(const __half* __restrict__ feat) {
    int gw = (blockIdx.x * blockDim.x + threadIdx.x) >> 5;
    int lane = threadIdx.x & 31;
    if (gw >= NN) return;
    int beg = g_rowptr[gw];
    int end = g_rowptr[gw + 1];
    float4 acc = make_float4(0.f, 0.f, 0.f, 0.f);
    for (int base = beg; base < end; base += 32) {
        int navail = end - base;
        if (navail > 32) navail = 32;
        int cidx = (base + lane < end) ? g_col[base + lane] : 0;
        int j = 0;
        for (; j + 8 <= navail; j += 8) {
            uint2 vv[8];
#pragma unroll
            for (int u = 0; u < 8; u++) {
                int sv = __shfl_sync(0xffffffffu, cidx, j + u);
                vv[u] = *(const uint2*)(feat + (size_t)sv * DIM + lane * 4);
            }
#pragma unroll
            for (int u = 0; u < 8; u++) {
                float2 f0 = __half22float2(*(__half2*)&vv[u].x);
                float2 f1 = __half22float2(*(__half2*)&vv[u].y);
                acc.x += f0.x; acc.y += f0.y; acc.z += f1.x; acc.w += f1.y;
            }
        }
        for (; j < navail; j++) {
            int sv = __shfl_sync(0xffffffffu, cidx, j);
            uint2 vv = *(const uint2*)(feat + (size_t)sv * DIM + lane * 4);
            float2 f0 = __half22float2(*(__half2*)&vv.x);
            float2 f1 = __half22float2(*(__half2*)&vv.y);
            acc.x += f0.x; acc.y += f0.y; acc.z += f1.x; acc.w += f1.y;
        }
    }
    float inv = 1.0f / fmaxf((float)(end - beg), 1.0f);
    acc.x *= inv; acc.y *= inv; acc.z *= inv; acc.w *= inv;
    size_t o = (size_t)gw * DIM + lane * 4;
    split_store4(g_ahi + o, g_alo + o, acc.x, acc.y, acc.z, acc.w);
}

// ---------------- mma.sync fused linear, fp16 2-term, cp.async pipelined ----------
// D[128x128] = [agg | X](K=256, fp16 hi+lo) @ W^T(fp16) + b
// 512 threads, 16 warps: wm = wid&7 (16 rows), wn = wid>>3 (64 cols).
__global__ void __launch_bounds__(512) k_lin_mma(
    const __half* __restrict__ Ahi, const __half* __restrict__ Alo,
    const __half* __restrict__ Xhi, const __half* __restrict__ Xlo,
    const __half* __restrict__ Bh,
    const float* __restrict__ bias, float* __restrict__ outf,
    __half* __restrict__ ohi, __half* __restrict__ olo, int do_relu) {
    extern __shared__ char dsm[];
    __shared__ float sbias[128];

    int tid = threadIdx.x;
    int wid = tid >> 5;
    int lane = tid & 31;
    int wm = wid & 7;
    int wn = wid >> 3;
    int n0 = blockIdx.x * TILE_M;

    uint32_t sbase = smem_u32(dsm);
    if (tid < 128) sbias[tid] = bias[tid];

    int a_off = (wm * 16 + (lane & 15)) * SAS_B + (lane >> 4) * 16;
    int b_off = (wn * 64 + (lane & 7) + ((lane >> 4) << 3)) * SAS_B + ((lane >> 3) & 1) * 16;

    float acc[8][4];
#pragma unroll
    for (int nt = 0; nt < 8; nt++)
#pragma unroll
        for (int p = 0; p < 4; p++) acc[nt][p] = 0.f;

    // stage issuer: chunk kc -> stage buffer sg (3 pieces: AH, AL, BH)
    auto stage_issue = [&](int kc, int sg) {
        const __half* ah = (kc < 2) ? Ahi : Xhi;
        const __half* al = (kc < 2) ? Alo : Xlo;
        int cb = (kc & 1) * 64;
        uint32_t sb = sbase + sg * STAGE_B;
#pragma unroll
        for (int it = 0; it < 6; it++) {
            int i = it * 512 + tid;
            int piece = i >> 10;          // 0:AH 1:AL 2:BH
            int rem = i & 1023;
            int r = rem >> 3, c8 = rem & 7;
            uint32_t dst = sb + piece * 18432 + r * SAS_B + c8 * 16;
            if (piece < 2) {
                int gn = n0 + r;
                const __half* src = (piece == 0) ? ah : al;
                int gnc = (gn < NN) ? gn : 0;   // clamped ptr; size-0 if OOB
                cpasync16(dst, src + (size_t)gnc * DIM + cb + c8 * 8, gn < NN);
            } else {
                cpasync16(dst, Bh + (size_t)r * 256 + kc * 64 + c8 * 8, 1);
            }
        }
        cp_commit();
    };

    stage_issue(0, 0);

    for (int kc = 0; kc < 4; kc++) {
        if (kc < 3) stage_issue(kc + 1, (kc + 1) & 1);
        if (kc < 3) cp_wait<1>(); else cp_wait<0>();
        __syncthreads();

        uint32_t sb = sbase + (kc & 1) * STAGE_B;
        uint32_t Abh = sb + OFF_AH + a_off;
        uint32_t Abl = sb + OFF_AL + a_off;
        uint32_t Bb  = sb + OFF_BH + b_off;
#pragma unroll
        for (int ks = 0; ks < 4; ks++) {
            uint32_t ah_fr[4], al_fr[4];
            ldmx4(ah_fr, Abh + ks * 32);
            ldmx4(al_fr, Abl + ks * 32);
            uint32_t bfr[8][2];
#pragma unroll
            for (int bp = 0; bp < 4; bp++) {
                uint32_t q[4];
                ldmx4(q, Bb + ks * 32 + bp * 16 * SAS_B);
                bfr[2 * bp][0] = q[0]; bfr[2 * bp][1] = q[1];
                bfr[2 * bp + 1][0] = q[2]; bfr[2 * bp + 1][1] = q[3];
            }
#pragma unroll
            for (int nt = 0; nt < 8; nt++)
                mma16816(acc[nt], ah_fr, bfr[nt]);
#pragma unroll
            for (int nt = 0; nt < 8; nt++)
                mma16816(acc[nt], al_fr, bfr[nt]);
        }
        __syncthreads();
    }

    // epilogue: bias + relu; layer1 -> fp16 hi/lo, layer2 -> fp32 out
    int cbase = wn * 64 + (lane & 3) * 2;
    int r0 = n0 + wm * 16 + (lane >> 2);
#pragma unroll
    for (int nt = 0; nt < 8; nt++) {
        int c = cbase + nt * 8;
        float bx = sbias[c], by = sbias[c + 1];
#pragma unroll
        for (int half = 0; half < 2; half++) {
            int r = r0 + half * 8;
            if (r >= NN) continue;
            float vx = acc[nt][2 * half] + bx;
            float vy = acc[nt][2 * half + 1] + by;
            if (do_relu) { vx = fmaxf(vx, 0.f); vy = fmaxf(vy, 0.f); }
            size_t o = (size_t)r * DIM + c;
            if (outf) {
                *(float2*)(outf + o) = make_float2(vx, vy);
            } else {
                __half h0 = __float2half_rn(vx);
                __half h1 = __float2half_rn(vy);
                __half l0 = __float2half_rn(vx - __half2float(h0));
                __half l1 = __float2half_rn(vy - __half2float(h1));
                *(uint32_t*)(ohi + o) = pack_h2(h0, h1);
                *(uint32_t*)(olo + o) = pack_h2(l0, l1);
            }
        }
    }
}

// ---------------- launch ----------------
extern "C" void kernel_launch(void* const* d_in, const int* in_sizes, int n_in,
                              void* d_out, int out_size) {
    const float* x   = (const float*)d_in[0];
    const void*  ei  = d_in[1];
    const float* W1l = (const float*)d_in[2];
    const float* b1  = (const float*)d_in[3];
    const float* W1r = (const float*)d_in[4];
    const float* W2l = (const float*)d_in[5];
    const float* b2  = (const float*)d_in[6];
    const float* W2r = (const float*)d_in[7];
    float*       out = (float*)d_out;

    cudaFuncSetAttribute(k_lin_mma, cudaFuncAttributeMaxDynamicSharedMemorySize, DYN_SMEM);

    __half *xh, *xl, *ah, *al, *hh, *hl, *w1h, *w2h;
    cudaGetSymbolAddress((void**)&xh, g_xhi);
    cudaGetSymbolAddress((void**)&xl, g_xlo);
    cudaGetSymbolAddress((void**)&ah, g_ahi);
    cudaGetSymbolAddress((void**)&al, g_alo);
    cudaGetSymbolAddress((void**)&hh, g_hhi);
    cudaGetSymbolAddress((void**)&hl, g_hlo);
    {
        __half (*wth)[128 * 256];
        cudaGetSymbolAddress((void**)&wth, g_wth);
        w1h = wth[0]; w2h = wth[1];
    }

    int nb_w = (NN * 32) / 256;                // warp per node

    // 0: pre (x split + W fp16 + zero + detect + barrier reset)
    k_pre<<<GRID_PRE, 256>>>(x, W1l, W1r, W2l, W2r, (const int*)ei);
    // 1: fused CSR build (hist + scan + fill)
    k_csr<<<NBLK_CSR, NTHR_CSR>>>(ei);
    // 2: layer-1 aggregation over fp16(x)
    k_agg<<<nb_w, 256>>>(xh);
    // 3: layer-1 linear  <- ncu capture target
    k_lin_mma<<<NTILES, 512, DYN_SMEM>>>(ah, al, xh, xl, w1h, b1, nullptr, hh, hl, 1);
    // 4: layer-2 aggregation over fp16(h)
    k_agg<<<nb_w, 256>>>(hh);
    // 5: layer-2 linear -> fp32 output
    k_lin_mma<<<NTILES, 512, DYN_SMEM>>>(ah, al, hh, hl, w2h, b2, out, nullptr, nullptr, 0);
}